// round 4
// baseline (speedup 1.0000x reference)
#include <cuda_runtime.h>
#include <cuda_fp16.h>
#include <cstdint>

#define HH 384
#define WW 384
#define CC 32
#define FF 32
#define KK 9
#define POS_PER_BLK 64
#define THREADS 512

// A: 128 rows x K'=576 fp16 (hi,lo interleaved) = 1152 B/row
#define ROWB 1152u
#define SMEM_A_OFF 0u
#define A_BYTES (128u * ROWB)                  // 147456
#define SMEM_B_OFF A_BYTES                     // 147456
#define B_BYTES (32u * ROWB)                   // 36864
#define SMEM_REC_OFF (SMEM_B_OFF + B_BYTES)    // 184320
#define REC_BYTES (576u * 32u)                 // 18432
#define SMEM_TOTAL (SMEM_REC_OFF + REC_BYTES)  // 202752

__device__ __forceinline__ uint32_t smem_u32(const void* p) {
    uint32_t a;
    asm("{ .reg .u64 t; cvta.to.shared.u64 t, %1; cvt.u32.u64 %0, t; }" : "=r"(a) : "l"(p));
    return a;
}

// 16B-granular XOR swizzle within each 128B group of a row.
// addr(row, cb) = row*1152 + (cb & ~127) + ((((cb>>4)&7) ^ (row&7)) << 4) + (cb & 15)

#define LDMATRIX_X4(r0, r1, r2, r3, addr)                                   \
    asm volatile("ldmatrix.sync.aligned.m8n8.x4.shared.b16 {%0,%1,%2,%3}, [%4];" \
                 : "=r"(r0), "=r"(r1), "=r"(r2), "=r"(r3) : "r"(addr))

#define MMA16816(d, a0, a1, a2, a3, b0, b1)                                 \
    asm volatile("mma.sync.aligned.m16n8k16.row.col.f32.f16.f16.f32 "       \
                 "{%0,%1,%2,%3}, {%4,%5,%6,%7}, {%8,%9}, {%0,%1,%2,%3};"    \
                 : "+f"((d)[0]), "+f"((d)[1]), "+f"((d)[2]), "+f"((d)[3])   \
                 : "r"(a0), "r"(a1), "r"(a2), "r"(a3), "r"(b0), "r"(b1))

// fp32 -> packed (fp16 hi in low half | fp16 lo in high half)
__device__ __forceinline__ uint32_t hilo_f16(float s) {
    __half h = __float2half_rn(s);
    float l = s - __half2float(h);
    uint32_t r;
    asm("cvt.rn.f16x2.f32 %0, %1, %2;" : "=r"(r) : "f"(l), "f"(s));
    return r;
}

extern __shared__ char smem[];

__global__ __launch_bounds__(THREADS, 1)
void deform_conv_hmma(const float* __restrict__ x,
                      const float* __restrict__ off,
                      const float* __restrict__ kern,
                      const float* __restrict__ bias,
                      float* __restrict__ out)
{
    const uint32_t sbase = smem_u32(smem);
    const int tid  = threadIdx.x;
    const int lane = tid & 31;
    const int w    = tid >> 5;            // 16 warps
    const int y    = blockIdx.y;
    const int xbase = blockIdx.x * POS_PER_BLK;

    // ---- B fill: B[n=f][k' pair at kc] = (w16, w16), kc = k*32 + c ----
    for (int i = tid; i < KK * CC * FF; i += THREADS) {
        const int f = i & 31;
        const int c = (i >> 5) & 31;
        const int k = i >> 10;
        const float wv = __ldg(kern + (k * 32 + c) * 32 + f);
        const __half wh = __float2half_rn(wv);
        const __half2 p = __halves2half2(wh, wh);
        const uint32_t addr = SMEM_B_OFF + (uint32_t)f * ROWB + (uint32_t)k * 128u +
                              ((((uint32_t)(c >> 2)) ^ ((uint32_t)f & 7u)) << 4) +
                              ((uint32_t)(c & 3)) * 4u;
        *(uint32_t*)(smem + addr) = *(uint32_t*)&p;
    }

    // ---- Stage 1: per-tap records (computed ONCE per tap, not per lane) ----
    // rec[j] = { base, dx, dy, pad, w00, w01, w10, w11 }, j = pos*9 + k
    #pragma unroll 1
    for (int j = tid; j < POS_PER_BLK * KK; j += THREADS) {
        const int pos = j / KK;
        const int k   = j - pos * KK;
        const int xcol = xbase + pos;
        const float2 o = __ldg((const float2*)(off + (size_t)(y * WW + xcol) * (KK * 2) + 2 * k));

        // padded coords: tap base (y + k/3, x + k%3), pad=1, clamp to [0,385]
        float yf = fminf(fmaxf((float)(y + k / 3) + o.y, 0.f), 385.f);
        float xf = fminf(fmaxf((float)(xcol + k % 3) + o.x, 0.f), 385.f);
        const float y0f = floorf(yf), x0f = floorf(xf);
        const int y0 = (int)y0f, x0 = (int)x0f;
        const int y1 = min(y0 + 1, 385), x1 = min(x0 + 1, 385);
        const float wy0 = (float)y1 - yf, wy1 = yf - y0f;
        const float wx0 = (float)x1 - xf, wx1 = xf - x0f;

        // validity (padded coord in [1,384] maps to interior); fold into weights
        const bool vy0 = (y0 >= 1) && (y0 <= 384);
        const bool vy1 = (y1 >= 1) && (y1 <= 384);
        const bool vx0 = (x0 >= 1) && (x0 <= 384);
        const bool vx1 = (x1 >= 1) && (x1 <= 384);
        const float w00 = (vy0 && vx0) ? wy0 * wx0 : 0.f;
        const float w01 = (vy0 && vx1) ? wy0 * wx1 : 0.f;
        const float w10 = (vy1 && vx0) ? wy1 * wx0 : 0.f;
        const float w11 = (vy1 && vx1) ? wy1 * wx1 : 0.f;

        // clamped interior coords for safe (weight-zeroed) addressing
        const int y0c = min(max(y0, 1), 384), y1c = min(max(y1, 1), 384);
        const int x0c = min(max(x0, 1), 384), x1c = min(max(x1, 1), 384);
        const int base = ((y0c - 1) * WW + (x0c - 1)) * CC;
        const int dx = (x1c - x0c) * CC;
        const int dy = (y1c - y0c) * WW * CC;

        uint4* rp = (uint4*)(smem + SMEM_REC_OFF + (uint32_t)j * 32u);
        rp[0] = make_uint4((uint32_t)base, (uint32_t)dx, (uint32_t)dy, 0u);
        float4* wp = (float4*)(rp + 1);
        wp[0] = make_float4(w00, w01, w10, w11);
    }

    __syncthreads();

    // ---- Stage 2: gather + blend -> split-fp16 A tile ----
    // warp w owns positions 4w..4w+3; lane = channel c.
    const int Bstride = HH * WW * CC;
    {
        const uint32_t sub = (uint32_t)(lane >> 2);
        const uint32_t lo4 = ((uint32_t)(lane & 3)) * 4u;
        #pragma unroll 1
        for (int p = 0; p < 4; ++p) {
            const int pos = w * 4 + p;
            const int r1 = 64 + pos;
            const uint32_t adb0 = SMEM_A_OFF + (uint32_t)pos * ROWB +
                                  ((sub ^ ((uint32_t)pos & 7u)) << 4) + lo4;
            const uint32_t adb1 = SMEM_A_OFF + (uint32_t)r1 * ROWB +
                                  ((sub ^ ((uint32_t)r1 & 7u)) << 4) + lo4;
            const char* recp = smem + SMEM_REC_OFF + (uint32_t)(pos * KK) * 32u;

            #pragma unroll
            for (int k = 0; k < KK; ++k) {
                const uint4  ri = *(const uint4*)(recp + k * 32);
                const float4 wv = *(const float4*)(recp + k * 32 + 16);
                const int a0i = (int)ri.x + lane;
                const int a1i = a0i + (int)ri.y;
                const int a2i = a0i + (int)ri.z;
                const int a3i = a1i + (int)ri.z;

                const float a00 = __ldg(x + a0i);
                const float a01 = __ldg(x + a1i);
                const float a10 = __ldg(x + a2i);
                const float a11 = __ldg(x + a3i);
                const float b00 = __ldg(x + Bstride + a0i);
                const float b01 = __ldg(x + Bstride + a1i);
                const float b10 = __ldg(x + Bstride + a2i);
                const float b11 = __ldg(x + Bstride + a3i);

                float s0 = wv.x * a00;
                s0 = fmaf(wv.y, a01, s0); s0 = fmaf(wv.z, a10, s0); s0 = fmaf(wv.w, a11, s0);
                float s1 = wv.x * b00;
                s1 = fmaf(wv.y, b01, s1); s1 = fmaf(wv.z, b10, s1); s1 = fmaf(wv.w, b11, s1);

                *(uint32_t*)(smem + adb0 + (uint32_t)k * 128u) = hilo_f16(s0);
                *(uint32_t*)(smem + adb1 + (uint32_t)k * 128u) = hilo_f16(s1);
            }
        }
    }

    __syncthreads();

    // ---- Phase 3: HMMA GEMM. Warps 0..7: rows 16w..16w+15, all N=32 ----
    if (w < 8) {
        const int rowbase = w * 16;

        const int rl  = rowbase + (lane & 7) + (lane & 8);      // A row for this lane
        const int kha = (lane >> 4) & 1;                        // A k-half (16B unit)
        const int nr0 = (lane & 7) + (((lane >> 4) & 1) << 3);  // B x4 #0 row
        const int nr1 = 16 + nr0;                               // B x4 #1 row
        const int khb = (lane >> 3) & 1;                        // B k-half

        const uint32_t a_row  = sbase + SMEM_A_OFF + (uint32_t)rl * ROWB;
        const uint32_t b_row0 = sbase + SMEM_B_OFF + (uint32_t)nr0 * ROWB;
        const uint32_t b_row1 = sbase + SMEM_B_OFF + (uint32_t)nr1 * ROWB;
        const uint32_t amask  = (uint32_t)rl & 7u;
        const uint32_t bmask0 = (uint32_t)nr0 & 7u;
        const uint32_t bmask1 = (uint32_t)nr1 & 7u;

        float d[16];
        #pragma unroll
        for (int i = 0; i < 16; ++i) d[i] = 0.f;

        #pragma unroll 2
        for (int s = 0; s < 36; ++s) {
            const uint32_t grp = (uint32_t)(s >> 2) * 128u;
            const uint32_t s2  = (uint32_t)(2 * s);

            uint32_t a0, a1, a2, a3;
            LDMATRIX_X4(a0, a1, a2, a3,
                        a_row + grp + ((((s2 + (uint32_t)kha) & 7u) ^ amask) << 4));
            uint32_t b0, b1, b2, b3;
            LDMATRIX_X4(b0, b1, b2, b3,
                        b_row0 + grp + ((((s2 + (uint32_t)khb) & 7u) ^ bmask0) << 4));
            uint32_t b4, b5, b6, b7;
            LDMATRIX_X4(b4, b5, b6, b7,
                        b_row1 + grp + ((((s2 + (uint32_t)khb) & 7u) ^ bmask1) << 4));

            MMA16816(d + 0,  a0, a1, a2, a3, b0, b1);   // n 0..7
            MMA16816(d + 4,  a0, a1, a2, a3, b2, b3);   // n 8..15
            MMA16816(d + 8,  a0, a1, a2, a3, b4, b5);   // n 16..23
            MMA16816(d + 12, a0, a1, a2, a3, b6, b7);   // n 24..31
        }

        // ---- Epilogue ----
        const int g = lane >> 2;
        const int t = lane & 3;
        const int R0 = rowbase + g;
        const int R1 = R0 + 8;
        const int b0r = R0 >> 6, p0r = R0 & 63;
        const int b1r = R1 >> 6, p1r = R1 & 63;
        float* o0 = out + ((size_t)(b0r * HH + y) * WW + xbase + p0r) * FF;
        float* o1 = out + ((size_t)(b1r * HH + y) * WW + xbase + p1r) * FF;

        #pragma unroll
        for (int nt = 0; nt < 4; ++nt) {
            const int f0 = nt * 8 + 2 * t;
            const float2 bv = __ldg((const float2*)(bias + f0));
            float2 v0 = make_float2(d[nt * 4 + 0] + bv.x, d[nt * 4 + 1] + bv.y);
            float2 v1 = make_float2(d[nt * 4 + 2] + bv.x, d[nt * 4 + 3] + bv.y);
            *(float2*)(o0 + f0) = v0;
            *(float2*)(o1 + f0) = v1;
        }
    }
}

extern "C" void kernel_launch(void* const* d_in, const int* in_sizes, int n_in,
                              void* d_out, int out_size)
{
    (void)in_sizes; (void)n_in; (void)out_size;
    const float* x    = (const float*)d_in[0];
    const float* off  = (const float*)d_in[1];
    const float* kern = (const float*)d_in[2];
    const float* bias = (const float*)d_in[3];
    float* out = (float*)d_out;

    cudaFuncSetAttribute(deform_conv_hmma,
                         cudaFuncAttributeMaxDynamicSharedMemorySize, SMEM_TOTAL);

    dim3 grid(WW / POS_PER_BLK, HH);
    deform_conv_hmma<<<grid, THREADS, SMEM_TOTAL>>>(x, off, kern, bias, out);
}

// round 5
// speedup vs baseline: 1.7831x; 1.7831x over previous
#include <cuda_runtime.h>
#include <cuda_fp16.h>
#include <cstdint>

#define HH 384
#define WW 384
#define CC 32
#define FF 32
#define KK 9
#define POS_PER_BLK 64
#define THREADS 512

// A: 128 rows x K'=576 fp16 (hi,lo interleaved) = 1152 B/row
#define ROWB 1152u
#define SMEM_A_OFF 0u
#define A_BYTES (128u * ROWB)                  // 147456
#define SMEM_B_OFF A_BYTES                     // 147456
#define B_BYTES (32u * ROWB)                   // 36864
#define SMEM_REC_OFF (SMEM_B_OFF + B_BYTES)    // 184320
#define REC_BYTES (576u * 32u)                 // 18432
#define SMEM_TOTAL (SMEM_REC_OFF + REC_BYTES)  // 202752

__device__ __forceinline__ uint32_t smem_u32(const void* p) {
    uint32_t a;
    asm("{ .reg .u64 t; cvta.to.shared.u64 t, %1; cvt.u32.u64 %0, t; }" : "=r"(a) : "l"(p));
    return a;
}

#define LDMATRIX_X4(r0, r1, r2, r3, addr)                                   \
    asm volatile("ldmatrix.sync.aligned.m8n8.x4.shared.b16 {%0,%1,%2,%3}, [%4];" \
                 : "=r"(r0), "=r"(r1), "=r"(r2), "=r"(r3) : "r"(addr))

#define MMA16816(d, a0, a1, a2, a3, b0, b1)                                 \
    asm volatile("mma.sync.aligned.m16n8k16.row.col.f32.f16.f16.f32 "       \
                 "{%0,%1,%2,%3}, {%4,%5,%6,%7}, {%8,%9}, {%0,%1,%2,%3};"    \
                 : "+f"((d)[0]), "+f"((d)[1]), "+f"((d)[2]), "+f"((d)[3])   \
                 : "r"(a0), "r"(a1), "r"(a2), "r"(a3), "r"(b0), "r"(b1))

// fp32 -> packed (fp16 hi in low half | fp16 lo in high half)
__device__ __forceinline__ uint32_t hilo_f16(float s) {
    __half h = __float2half_rn(s);
    float l = s - __half2float(h);
    uint32_t r;
    asm("cvt.rn.f16x2.f32 %0, %1, %2;" : "=r"(r) : "f"(l), "f"(s));
    return r;
}

extern __shared__ char smem[];

__global__ __launch_bounds__(THREADS, 1)
void deform_conv_hmma(const float* __restrict__ x,
                      const float* __restrict__ off,
                      const float* __restrict__ kern,
                      const float* __restrict__ bias,
                      float* __restrict__ out)
{
    const uint32_t sbase = smem_u32(smem);
    const int tid  = threadIdx.x;
    const int lane = tid & 31;
    const int w    = tid >> 5;            // 16 warps
    const int y    = blockIdx.y;
    const int xbase = blockIdx.x * POS_PER_BLK;

    // ---- B fill: B[n=f][k' pair at kc] = (w16, w16), kc = k*32 + c ----
    for (int i = tid; i < KK * CC * FF; i += THREADS) {
        const int f = i & 31;
        const int c = (i >> 5) & 31;
        const int k = i >> 10;
        const float wv = __ldg(kern + (k * 32 + c) * 32 + f);
        const __half wh = __float2half_rn(wv);
        const __half2 p = __halves2half2(wh, wh);
        const uint32_t addr = SMEM_B_OFF + (uint32_t)f * ROWB + (uint32_t)k * 128u +
                              ((((uint32_t)(c >> 2)) ^ ((uint32_t)f & 7u)) << 4) +
                              ((uint32_t)(c & 3)) * 4u;
        *(uint32_t*)(smem + addr) = *(uint32_t*)&p;
    }

    // ---- Stage 1: per-tap records (ONE thread per tap) ----
    // rec[j] = { i00, i01, i10, i11, w00, w01, w10, w11 }, j = pos*9 + k
    #pragma unroll 1
    for (int j = tid; j < POS_PER_BLK * KK; j += THREADS) {
        const int pos = j / KK;
        const int k   = j - pos * KK;
        const int xcol = xbase + pos;
        const float2 o = __ldg((const float2*)(off + (size_t)(y * WW + xcol) * (KK * 2) + 2 * k));

        // padded coords: tap base (y + k/3, x + k%3), pad=1, clamp to [0,385]
        float yf = fminf(fmaxf((float)(y + k / 3) + o.y, 0.f), 385.f);
        float xf = fminf(fmaxf((float)(xcol + k % 3) + o.x, 0.f), 385.f);
        const float y0f = floorf(yf), x0f = floorf(xf);
        const int y0 = (int)y0f, x0 = (int)x0f;
        const int y1 = min(y0 + 1, 385), x1 = min(x0 + 1, 385);
        const float wy0 = (float)y1 - yf, wy1 = yf - y0f;
        const float wx0 = (float)x1 - xf, wx1 = xf - x0f;

        const bool vy0 = (y0 >= 1) && (y0 <= 384);
        const bool vy1 = (y1 >= 1) && (y1 <= 384);
        const bool vx0 = (x0 >= 1) && (x0 <= 384);
        const bool vx1 = (x1 >= 1) && (x1 <= 384);
        const float w00 = (vy0 && vx0) ? wy0 * wx0 : 0.f;
        const float w01 = (vy0 && vx1) ? wy0 * wx1 : 0.f;
        const float w10 = (vy1 && vx0) ? wy1 * wx0 : 0.f;
        const float w11 = (vy1 && vx1) ? wy1 * wx1 : 0.f;

        // clamped interior coords for safe (weight-zeroed) addressing
        const int y0c = min(max(y0, 1), 384), y1c = min(max(y1, 1), 384);
        const int x0c = min(max(x0, 1), 384), x1c = min(max(x1, 1), 384);
        const int i00 = ((y0c - 1) * WW + (x0c - 1)) * CC;
        const int i01 = ((y0c - 1) * WW + (x1c - 1)) * CC;
        const int i10 = ((y1c - 1) * WW + (x0c - 1)) * CC;
        const int i11 = ((y1c - 1) * WW + (x1c - 1)) * CC;

        uint4* rp = (uint4*)(smem + SMEM_REC_OFF + (uint32_t)j * 32u);
        rp[0] = make_uint4((uint32_t)i00, (uint32_t)i01, (uint32_t)i10, (uint32_t)i11);
        ((float4*)rp)[1] = make_float4(w00, w01, w10, w11);
    }

    __syncthreads();

    // ---- Stage 2: gather + blend -> split-fp16 A tile (3-tap batches, high MLP) ----
    // warp w owns positions 4w..4w+3; lane = channel c.
    const int Bstride = HH * WW * CC;
    {
        const uint32_t sub = (uint32_t)(lane >> 2);
        const uint32_t lo4 = ((uint32_t)(lane & 3)) * 4u;
        #pragma unroll 1
        for (int p = 0; p < 4; ++p) {
            const int pos = w * 4 + p;
            const int r1 = 64 + pos;
            const uint32_t adb0 = SMEM_A_OFF + (uint32_t)pos * ROWB +
                                  ((sub ^ ((uint32_t)pos & 7u)) << 4) + lo4;
            const uint32_t adb1 = SMEM_A_OFF + (uint32_t)r1 * ROWB +
                                  ((sub ^ ((uint32_t)r1 & 7u)) << 4) + lo4;
            const char* recp = smem + SMEM_REC_OFF + (uint32_t)(pos * KK) * 32u;

            #pragma unroll
            for (int kb = 0; kb < 3; ++kb) {
                // load 3 records, compute 12 indices
                uint4  ri[3];
                float4 wv[3];
                #pragma unroll
                for (int t = 0; t < 3; ++t) {
                    const int k = kb * 3 + t;
                    ri[t] = *(const uint4*)(recp + k * 32);
                    wv[t] = *(const float4*)(recp + k * 32 + 16);
                }
                // issue all 24 loads back-to-back (independent)
                float va[3][4], vb[3][4];
                #pragma unroll
                for (int t = 0; t < 3; ++t) {
                    const int j0 = (int)ri[t].x + lane;
                    const int j1 = (int)ri[t].y + lane;
                    const int j2 = (int)ri[t].z + lane;
                    const int j3 = (int)ri[t].w + lane;
                    va[t][0] = __ldg(x + j0);
                    va[t][1] = __ldg(x + j1);
                    va[t][2] = __ldg(x + j2);
                    va[t][3] = __ldg(x + j3);
                    vb[t][0] = __ldg(x + Bstride + j0);
                    vb[t][1] = __ldg(x + Bstride + j1);
                    vb[t][2] = __ldg(x + Bstride + j2);
                    vb[t][3] = __ldg(x + Bstride + j3);
                }
                // blend + convert + store
                #pragma unroll
                for (int t = 0; t < 3; ++t) {
                    const int k = kb * 3 + t;
                    float s0 = wv[t].x * va[t][0];
                    s0 = fmaf(wv[t].y, va[t][1], s0);
                    s0 = fmaf(wv[t].z, va[t][2], s0);
                    s0 = fmaf(wv[t].w, va[t][3], s0);
                    float s1 = wv[t].x * vb[t][0];
                    s1 = fmaf(wv[t].y, vb[t][1], s1);
                    s1 = fmaf(wv[t].z, vb[t][2], s1);
                    s1 = fmaf(wv[t].w, vb[t][3], s1);
                    *(uint32_t*)(smem + adb0 + (uint32_t)k * 128u) = hilo_f16(s0);
                    *(uint32_t*)(smem + adb1 + (uint32_t)k * 128u) = hilo_f16(s1);
                }
            }
        }
    }

    __syncthreads();

    // ---- Phase 3: HMMA GEMM. Warps 0..7: rows 16w..16w+15, all N=32 ----
    if (w < 8) {
        const int rowbase = w * 16;

        const int rl  = rowbase + (lane & 7) + (lane & 8);      // A row for this lane
        const int kha = (lane >> 4) & 1;                        // A k-half (16B unit)
        const int nr0 = (lane & 7) + (((lane >> 4) & 1) << 3);  // B x4 #0 row
        const int nr1 = 16 + nr0;                               // B x4 #1 row
        const int khb = (lane >> 3) & 1;                        // B k-half

        const uint32_t a_row  = sbase + SMEM_A_OFF + (uint32_t)rl * ROWB;
        const uint32_t b_row0 = sbase + SMEM_B_OFF + (uint32_t)nr0 * ROWB;
        const uint32_t b_row1 = sbase + SMEM_B_OFF + (uint32_t)nr1 * ROWB;
        const uint32_t amask  = (uint32_t)rl & 7u;
        const uint32_t bmask0 = (uint32_t)nr0 & 7u;
        const uint32_t bmask1 = (uint32_t)nr1 & 7u;

        float d[16];
        #pragma unroll
        for (int i = 0; i < 16; ++i) d[i] = 0.f;

        #pragma unroll 2
        for (int s = 0; s < 36; ++s) {
            const uint32_t grp = (uint32_t)(s >> 2) * 128u;
            const uint32_t s2  = (uint32_t)(2 * s);

            uint32_t a0, a1, a2, a3;
            LDMATRIX_X4(a0, a1, a2, a3,
                        a_row + grp + ((((s2 + (uint32_t)kha) & 7u) ^ amask) << 4));
            uint32_t b0, b1, b2, b3;
            LDMATRIX_X4(b0, b1, b2, b3,
                        b_row0 + grp + ((((s2 + (uint32_t)khb) & 7u) ^ bmask0) << 4));
            uint32_t b4, b5, b6, b7;
            LDMATRIX_X4(b4, b5, b6, b7,
                        b_row1 + grp + ((((s2 + (uint32_t)khb) & 7u) ^ bmask1) << 4));

            MMA16816(d + 0,  a0, a1, a2, a3, b0, b1);   // n 0..7
            MMA16816(d + 4,  a0, a1, a2, a3, b2, b3);   // n 8..15
            MMA16816(d + 8,  a0, a1, a2, a3, b4, b5);   // n 16..23
            MMA16816(d + 12, a0, a1, a2, a3, b6, b7);   // n 24..31
        }

        // ---- Epilogue ----
        const int g = lane >> 2;
        const int t = lane & 3;
        const int R0 = rowbase + g;
        const int R1 = R0 + 8;
        const int b0r = R0 >> 6, p0r = R0 & 63;
        const int b1r = R1 >> 6, p1r = R1 & 63;
        float* o0 = out + ((size_t)(b0r * HH + y) * WW + xbase + p0r) * FF;
        float* o1 = out + ((size_t)(b1r * HH + y) * WW + xbase + p1r) * FF;

        #pragma unroll
        for (int nt = 0; nt < 4; ++nt) {
            const int f0 = nt * 8 + 2 * t;
            const float2 bv = __ldg((const float2*)(bias + f0));
            float2 v0 = make_float2(d[nt * 4 + 0] + bv.x, d[nt * 4 + 1] + bv.y);
            float2 v1 = make_float2(d[nt * 4 + 2] + bv.x, d[nt * 4 + 3] + bv.y);
            *(float2*)(o0 + f0) = v0;
            *(float2*)(o1 + f0) = v1;
        }
    }
}

extern "C" void kernel_launch(void* const* d_in, const int* in_sizes, int n_in,
                              void* d_out, int out_size)
{
    (void)in_sizes; (void)n_in; (void)out_size;
    const float* x    = (const float*)d_in[0];
    const float* off  = (const float*)d_in[1];
    const float* kern = (const float*)d_in[2];
    const float* bias = (const float*)d_in[3];
    float* out = (float*)d_out;

    cudaFuncSetAttribute(deform_conv_hmma,
                         cudaFuncAttributeMaxDynamicSharedMemorySize, SMEM_TOTAL);

    dim3 grid(WW / POS_PER_BLK, HH);
    deform_conv_hmma<<<grid, THREADS, SMEM_TOTAL>>>(x, off, kern, bias, out);
}

// round 6
// speedup vs baseline: 1.8766x; 1.0525x over previous
#include <cuda_runtime.h>
#include <cuda_fp16.h>
#include <cstdint>

#define HH 384
#define WW 384
#define CC 32
#define FF 32
#define KK 9
#define POS_PER_BLK 32
#define THREADS 512

// A: 64 rows x K'=576 fp16 = 1152 B/row. Layout: hi block cols [0,288), lo block [288,576).
#define ROWB 1152u
#define SMEM_A_OFF 0u
#define A_BYTES (64u * ROWB)                   // 73728
// B: 32 rows x 288 fp16 (single copy), row padded to 640 B for swizzle groups
#define BROWB 640u
#define SMEM_B_OFF A_BYTES                     // 73728
#define B_BYTES (32u * BROWB)                  // 20480
#define SMEM_REC_OFF (SMEM_B_OFF + B_BYTES)    // 94208
#define REC_BYTES (288u * 32u)                 // 9216
#define SMEM_TOTAL (SMEM_REC_OFF + REC_BYTES)  // 103424

__device__ __forceinline__ uint32_t smem_u32(const void* p) {
    uint32_t a;
    asm("{ .reg .u64 t; cvta.to.shared.u64 t, %1; cvt.u32.u64 %0, t; }" : "=r"(a) : "l"(p));
    return a;
}

#define LDMATRIX_X4(r0, r1, r2, r3, addr)                                   \
    asm volatile("ldmatrix.sync.aligned.m8n8.x4.shared.b16 {%0,%1,%2,%3}, [%4];" \
                 : "=r"(r0), "=r"(r1), "=r"(r2), "=r"(r3) : "r"(addr))

#define MMA16816(d, a0, a1, a2, a3, b0, b1)                                 \
    asm volatile("mma.sync.aligned.m16n8k16.row.col.f32.f16.f16.f32 "       \
                 "{%0,%1,%2,%3}, {%4,%5,%6,%7}, {%8,%9}, {%0,%1,%2,%3};"    \
                 : "+f"((d)[0]), "+f"((d)[1]), "+f"((d)[2]), "+f"((d)[3])   \
                 : "r"(a0), "r"(a1), "r"(a2), "r"(a3), "r"(b0), "r"(b1))

extern __shared__ char smem[];

__global__ __launch_bounds__(THREADS, 2)
void deform_conv_hmma(const float* __restrict__ x,
                      const float* __restrict__ off,
                      const float* __restrict__ kern,
                      const float* __restrict__ bias,
                      float* __restrict__ out)
{
    const uint32_t sbase = smem_u32(smem);
    const int tid  = threadIdx.x;
    const int lane = tid & 31;
    const int w    = tid >> 5;            // 16 warps
    const int y    = blockIdx.y;
    const int xbase = blockIdx.x * POS_PER_BLK;

    // ---- B fill: single fp16 copy, B[f][kc], kc = k*32 + c ----
    for (int i = tid; i < KK * CC * FF; i += THREADS) {
        const int f = i & 31;
        const int c = (i >> 5) & 31;
        const int k = i >> 10;
        const __half wh = __float2half_rn(__ldg(kern + (k * 32 + c) * 32 + f));
        const uint32_t kb = (uint32_t)(k * 32 + c) * 2u;
        const uint32_t addr = SMEM_B_OFF + (uint32_t)f * BROWB + (kb & ~127u) +
                              ((((kb >> 4) & 7u) ^ ((uint32_t)f & 7u)) << 4) + (kb & 15u);
        *(__half*)(smem + addr) = wh;
    }

    // ---- Stage 1: per-tap records (ONE thread per tap) ----
    // rec[j] = { i00, i01, i10, i11, w00, w01, w10, w11 }, j = pos*9 + k
    if (tid < POS_PER_BLK * KK) {
        const int j = tid;
        const int pos = j / KK;
        const int k   = j - pos * KK;
        const int xcol = xbase + pos;
        const float2 o = __ldg((const float2*)(off + (size_t)(y * WW + xcol) * (KK * 2) + 2 * k));

        // padded coords: tap base (y + k/3, x + k%3), pad=1, clamp to [0,385]
        float yf = fminf(fmaxf((float)(y + k / 3) + o.y, 0.f), 385.f);
        float xf = fminf(fmaxf((float)(xcol + k % 3) + o.x, 0.f), 385.f);
        const float y0f = floorf(yf), x0f = floorf(xf);
        const int y0 = (int)y0f, x0 = (int)x0f;
        const int y1 = min(y0 + 1, 385), x1 = min(x0 + 1, 385);
        const float wy0 = (float)y1 - yf, wy1 = yf - y0f;
        const float wx0 = (float)x1 - xf, wx1 = xf - x0f;

        const bool vy0 = (y0 >= 1) && (y0 <= 384);
        const bool vy1 = (y1 >= 1) && (y1 <= 384);
        const bool vx0 = (x0 >= 1) && (x0 <= 384);
        const bool vx1 = (x1 >= 1) && (x1 <= 384);
        const float w00 = (vy0 && vx0) ? wy0 * wx0 : 0.f;
        const float w01 = (vy0 && vx1) ? wy0 * wx1 : 0.f;
        const float w10 = (vy1 && vx0) ? wy1 * wx0 : 0.f;
        const float w11 = (vy1 && vx1) ? wy1 * wx1 : 0.f;

        const int y0c = min(max(y0, 1), 384), y1c = min(max(y1, 1), 384);
        const int x0c = min(max(x0, 1), 384), x1c = min(max(x1, 1), 384);
        const int i00 = ((y0c - 1) * WW + (x0c - 1)) * CC;
        const int i01 = ((y0c - 1) * WW + (x1c - 1)) * CC;
        const int i10 = ((y1c - 1) * WW + (x0c - 1)) * CC;
        const int i11 = ((y1c - 1) * WW + (x1c - 1)) * CC;

        uint4* rp = (uint4*)(smem + SMEM_REC_OFF + (uint32_t)j * 32u);
        rp[0] = make_uint4((uint32_t)i00, (uint32_t)i01, (uint32_t)i10, (uint32_t)i11);
        ((float4*)rp)[1] = make_float4(w00, w01, w10, w11);
    }

    __syncthreads();

    // ---- Stage 2: gather + blend -> split-fp16 A tile (3-tap batches) ----
    // warp w owns positions 2w, 2w+1; lane = channel c.
    // A row = batch*32 + pos; hi at col kc, lo at col 288+kc.
    const int Bstride = HH * WW * CC;
    {
        const uint32_t lanehw = ((uint32_t)lane & 7u) << 4;   // 16B sub-block of lane pair
        #pragma unroll
        for (int p = 0; p < 2; ++p) {
            const int pos = w * 2 + p;
            const int r1 = 32 + pos;
            // lane c stores 2B at col c (hi) and col 288+c (lo); kb_hi = (k*32+c)*2
            const char* recp = smem + SMEM_REC_OFF + (uint32_t)(pos * KK) * 32u;

            #pragma unroll
            for (int kb3 = 0; kb3 < 3; ++kb3) {
                uint4  ri[3];
                float4 wv[3];
                #pragma unroll
                for (int t = 0; t < 3; ++t) {
                    const int k = kb3 * 3 + t;
                    ri[t] = *(const uint4*)(recp + k * 32);
                    wv[t] = *(const float4*)(recp + k * 32 + 16);
                }
                float va[3][4], vb[3][4];
                #pragma unroll
                for (int t = 0; t < 3; ++t) {
                    const int j0 = (int)ri[t].x + lane;
                    const int j1 = (int)ri[t].y + lane;
                    const int j2 = (int)ri[t].z + lane;
                    const int j3 = (int)ri[t].w + lane;
                    va[t][0] = __ldg(x + j0);
                    va[t][1] = __ldg(x + j1);
                    va[t][2] = __ldg(x + j2);
                    va[t][3] = __ldg(x + j3);
                    vb[t][0] = __ldg(x + Bstride + j0);
                    vb[t][1] = __ldg(x + Bstride + j1);
                    vb[t][2] = __ldg(x + Bstride + j2);
                    vb[t][3] = __ldg(x + Bstride + j3);
                }
                #pragma unroll
                for (int t = 0; t < 3; ++t) {
                    const int k = kb3 * 3 + t;
                    float s0 = wv[t].x * va[t][0];
                    s0 = fmaf(wv[t].y, va[t][1], s0);
                    s0 = fmaf(wv[t].z, va[t][2], s0);
                    s0 = fmaf(wv[t].w, va[t][3], s0);
                    float s1 = wv[t].x * vb[t][0];
                    s1 = fmaf(wv[t].y, vb[t][1], s1);
                    s1 = fmaf(wv[t].z, vb[t][2], s1);
                    s1 = fmaf(wv[t].w, vb[t][3], s1);

                    const __half h0 = __float2half_rn(s0);
                    const __half l0 = __float2half_rn(s0 - __half2float(h0));
                    const __half h1 = __float2half_rn(s1);
                    const __half l1 = __float2half_rn(s1 - __half2float(h1));

                    // hi store: kb = (k*32+lane)*2 ; lo store: kb + 576
                    const uint32_t kbh = ((uint32_t)(k * 32 + lane)) * 2u;
                    const uint32_t kbl = kbh + 576u;
                    const uint32_t gh = kbh & ~127u, gl = kbl & ~127u;
                    const uint32_t shh = (kbh >> 4) & 7u, shl = (kbl >> 4) & 7u;
                    const uint32_t r0m = (uint32_t)pos & 7u, r1m = (uint32_t)r1 & 7u;
                    const uint32_t a0 = SMEM_A_OFF + (uint32_t)pos * ROWB;
                    const uint32_t a1 = SMEM_A_OFF + (uint32_t)r1 * ROWB;
                    *(__half*)(smem + a0 + gh + ((shh ^ r0m) << 4) + (kbh & 15u)) = h0;
                    *(__half*)(smem + a0 + gl + ((shl ^ r0m) << 4) + (kbl & 15u)) = l0;
                    *(__half*)(smem + a1 + gh + ((shh ^ r1m) << 4) + (kbh & 15u)) = h1;
                    *(__half*)(smem + a1 + gl + ((shl ^ r1m) << 4) + (kbl & 15u)) = l1;
                }
            }
            (void)lanehw;
        }
    }

    __syncthreads();

    // ---- Phase 3: HMMA GEMM. Warps 0..7: warp = (rg = w&3 -> rows 16rg, nh = w>>2 -> n 16nh) ----
    if (w < 8) {
        const int rg = w & 3;
        const int nh = w >> 2;
        const int rowbase = rg * 16;

        const int rl  = rowbase + (lane & 7) + (lane & 8);      // A row
        const int kha = (lane >> 4) & 1;                        // A k-half
        const int nr  = nh * 16 + (lane & 7) + (((lane >> 4) & 1) << 3);  // B row
        const int khb = (lane >> 3) & 1;                        // B k-half

        const uint32_t a_row = sbase + SMEM_A_OFF + (uint32_t)rl * ROWB;
        const uint32_t b_row = sbase + SMEM_B_OFF + (uint32_t)nr * BROWB;
        const uint32_t amask = (uint32_t)rl & 7u;
        const uint32_t bmask = (uint32_t)nr & 7u;

        float d[8];
        #pragma unroll
        for (int i = 0; i < 8; ++i) d[i] = 0.f;

        #pragma unroll 2
        for (int half = 0; half < 2; ++half) {
            #pragma unroll 3
            for (int s = 0; s < 18; ++s) {
                // A: kb = half*576 + 32s (+16 kha)
                const uint32_t kba = (uint32_t)half * 576u + (uint32_t)s * 32u +
                                     (uint32_t)kha * 16u;
                const uint32_t aaddr = a_row + (kba & ~127u) +
                                       ((((kba >> 4) & 7u) ^ amask) << 4);
                // B: kb = 32s (+16 khb)  (same tile both halves)
                const uint32_t kbb = (uint32_t)s * 32u + (uint32_t)khb * 16u;
                const uint32_t baddr = b_row + (kbb & ~127u) +
                                       ((((kbb >> 4) & 7u) ^ bmask) << 4);

                uint32_t a0, a1, a2, a3;
                LDMATRIX_X4(a0, a1, a2, a3, aaddr);
                uint32_t b0, b1, b2, b3;
                LDMATRIX_X4(b0, b1, b2, b3, baddr);

                MMA16816(d + 0, a0, a1, a2, a3, b0, b1);   // n 16nh+0..7
                MMA16816(d + 4, a0, a1, a2, a3, b2, b3);   // n 16nh+8..15
            }
        }

        // ---- Epilogue ----
        const int g = lane >> 2;
        const int t = lane & 3;
        const int R0 = rowbase + g;
        const int R1 = R0 + 8;
        const int b0r = R0 >> 5, p0r = R0 & 31;
        const int b1r = R1 >> 5, p1r = R1 & 31;
        float* o0 = out + ((size_t)(b0r * HH + y) * WW + xbase + p0r) * FF + nh * 16;
        float* o1 = out + ((size_t)(b1r * HH + y) * WW + xbase + p1r) * FF + nh * 16;

        #pragma unroll
        for (int nt = 0; nt < 2; ++nt) {
            const int f0 = nt * 8 + 2 * t;
            const float2 bv = __ldg((const float2*)(bias + nh * 16 + f0));
            float2 v0 = make_float2(d[nt * 4 + 0] + bv.x, d[nt * 4 + 1] + bv.y);
            float2 v1 = make_float2(d[nt * 4 + 2] + bv.x, d[nt * 4 + 3] + bv.y);
            *(float2*)(o0 + f0) = v0;
            *(float2*)(o1 + f0) = v1;
        }
    }
}

extern "C" void kernel_launch(void* const* d_in, const int* in_sizes, int n_in,
                              void* d_out, int out_size)
{
    (void)in_sizes; (void)n_in; (void)out_size;
    const float* x    = (const float*)d_in[0];
    const float* off  = (const float*)d_in[1];
    const float* kern = (const float*)d_in[2];
    const float* bias = (const float*)d_in[3];
    float* out = (float*)d_out;

    cudaFuncSetAttribute(deform_conv_hmma,
                         cudaFuncAttributeMaxDynamicSharedMemorySize, SMEM_TOTAL);

    dim3 grid(WW / POS_PER_BLK, HH);
    deform_conv_hmma<<<grid, THREADS, SMEM_TOTAL>>>(x, off, kern, bias, out);
}

// round 7
// speedup vs baseline: 2.0421x; 1.0882x over previous
#include <cuda_runtime.h>
#include <cuda_fp16.h>
#include <cstdint>

#define HH 384
#define WW 384
#define CC 32
#define FF 32
#define KK 9
#define POS_PER_BLK 32
#define THREADS 512

// A: 64 rows x K'=576 fp16 (hi,lo interleaved) = 1152 B/row
#define ROWB 1152u
#define SMEM_A_OFF 0u
#define A_BYTES (64u * ROWB)                   // 73728
#define ROW1_DELTA (32u * ROWB)                // batch-1 row offset within A
// B: 32 rows x 576 (w,w) fp16 = 1152 B/row (duplicated along K')
#define SMEM_B_OFF A_BYTES                     // 73728
#define B_BYTES (32u * ROWB)                   // 36864
#define SMEM_REC_OFF (SMEM_B_OFF + B_BYTES)    // 110592
#define REC_BYTES (288u * 16u)                 // 4608
#define SMEM_TOTAL (SMEM_REC_OFF + REC_BYTES)  // 115200

__device__ __forceinline__ uint32_t smem_u32(const void* p) {
    uint32_t a;
    asm("{ .reg .u64 t; cvta.to.shared.u64 t, %1; cvt.u32.u64 %0, t; }" : "=r"(a) : "l"(p));
    return a;
}

#define LDMATRIX_X4(r0, r1, r2, r3, addr)                                   \
    asm volatile("ldmatrix.sync.aligned.m8n8.x4.shared.b16 {%0,%1,%2,%3}, [%4];" \
                 : "=r"(r0), "=r"(r1), "=r"(r2), "=r"(r3) : "r"(addr))

#define MMA16816(d, a0, a1, a2, a3, b0, b1)                                 \
    asm volatile("mma.sync.aligned.m16n8k16.row.col.f32.f16.f16.f32 "       \
                 "{%0,%1,%2,%3}, {%4,%5,%6,%7}, {%8,%9}, {%0,%1,%2,%3};"    \
                 : "+f"((d)[0]), "+f"((d)[1]), "+f"((d)[2]), "+f"((d)[3])   \
                 : "r"(a0), "r"(a1), "r"(a2), "r"(a3), "r"(b0), "r"(b1))

// fp32 -> packed (fp16 hi in low half | fp16 lo in high half)
__device__ __forceinline__ uint32_t hilo_f16(float s) {
    __half h = __float2half_rn(s);
    float l = s - __half2float(h);
    uint32_t r;
    asm("cvt.rn.f16x2.f32 %0, %1, %2;" : "=r"(r) : "f"(l), "f"(s));
    return r;
}

extern __shared__ char smem[];

__global__ __launch_bounds__(THREADS, 2)
void deform_conv_hmma(const float* __restrict__ x,
                      const float* __restrict__ off,
                      const float* __restrict__ kern,
                      const float* __restrict__ bias,
                      float* __restrict__ out)
{
    const uint32_t sbase = smem_u32(smem);
    const int tid  = threadIdx.x;
    const int lane = tid & 31;
    const int w    = tid >> 5;            // 16 warps
    const int y    = blockIdx.y;
    const int xbase = blockIdx.x * POS_PER_BLK;

    // ---- B fill: B[f][k' pair at kc] = (w16, w16), kc = k*32 + c ----
    // byte offset within row: kb = k*128 + c*4; swizzle: 16B block ^= (f&7)
    for (int i = tid; i < KK * CC * FF; i += THREADS) {
        const int f = i & 31;
        const int c = (i >> 5) & 31;
        const int k = i >> 10;
        const __half wh = __float2half_rn(__ldg(kern + (k * 32 + c) * 32 + f));
        const __half2 p = __halves2half2(wh, wh);
        const uint32_t addr = SMEM_B_OFF + (uint32_t)f * ROWB + (uint32_t)k * 128u +
                              ((((uint32_t)(c >> 2)) ^ ((uint32_t)f & 7u)) << 4) +
                              ((uint32_t)(c & 3)) * 4u;
        *(uint32_t*)(smem + addr) = *(uint32_t*)&p;
    }

    // ---- Stage 1: per-tap 16B records (ONE thread per tap) ----
    // rec[j] = { i00, dx|dy<<16, (w00,w01) f16x2, (w10,w11) f16x2 }, j = pos*9 + k
    if (tid < POS_PER_BLK * KK) {
        const int j = tid;
        const int pos = j / KK;
        const int k   = j - pos * KK;
        const int xcol = xbase + pos;
        const float2 o = __ldg((const float2*)(off + (size_t)(y * WW + xcol) * (KK * 2) + 2 * k));

        // padded coords: tap base (y + k/3, x + k%3), pad=1, clamp to [0,385]
        float yf = fminf(fmaxf((float)(y + k / 3) + o.y, 0.f), 385.f);
        float xf = fminf(fmaxf((float)(xcol + k % 3) + o.x, 0.f), 385.f);
        const float y0f = floorf(yf), x0f = floorf(xf);
        const int y0 = (int)y0f, x0 = (int)x0f;
        const int y1 = min(y0 + 1, 385), x1 = min(x0 + 1, 385);
        const float wy0 = (float)y1 - yf, wy1 = yf - y0f;
        const float wx0 = (float)x1 - xf, wx1 = xf - x0f;

        const bool vy0 = (y0 >= 1) && (y0 <= 384);
        const bool vy1 = (y1 >= 1) && (y1 <= 384);
        const bool vx0 = (x0 >= 1) && (x0 <= 384);
        const bool vx1 = (x1 >= 1) && (x1 <= 384);
        const float w00 = (vy0 && vx0) ? wy0 * wx0 : 0.f;
        const float w01 = (vy0 && vx1) ? wy0 * wx1 : 0.f;
        const float w10 = (vy1 && vx0) ? wy1 * wx0 : 0.f;
        const float w11 = (vy1 && vx1) ? wy1 * wx1 : 0.f;

        const int y0c = min(max(y0, 1), 384), y1c = min(max(y1, 1), 384);
        const int x0c = min(max(x0, 1), 384), x1c = min(max(x1, 1), 384);
        const int i00 = ((y0c - 1) * WW + (x0c - 1)) * CC;
        const uint32_t dx = (uint32_t)((x1c - x0c) * CC);            // 0 or 32
        const uint32_t dy = (uint32_t)((y1c - y0c) * WW * CC);       // 0 or 12288

        const __half2 wA = __floats2half2_rn(w00, w01);
        const __half2 wB = __floats2half2_rn(w10, w11);
        uint4 rec;
        rec.x = (uint32_t)i00;
        rec.y = dx | (dy << 16);
        rec.z = *(const uint32_t*)&wA;
        rec.w = *(const uint32_t*)&wB;
        *(uint4*)(smem + SMEM_REC_OFF + (uint32_t)j * 16u) = rec;
    }

    __syncthreads();

    // ---- Stage 2: gather + blend -> interleaved split-fp16 A tile ----
    // warp w owns positions 2w, 2w+1; lane = channel c.
    // store: 1 STS.32 per (tap,batch); addr = rowbase + k*128 (swizzle constant per pos)
    const int Bstride = HH * WW * CC;
    {
        const uint32_t swz = ((((uint32_t)lane >> 2)) << 4);   // ^ (row&7)<<4 applied below
        #pragma unroll
        for (int p = 0; p < 2; ++p) {
            const int pos = w * 2 + p;
            const uint32_t base0 = SMEM_A_OFF + (uint32_t)pos * ROWB +
                                   (swz ^ (((uint32_t)pos & 7u) << 4)) +
                                   ((uint32_t)lane & 3u) * 4u;
            const char* recp = smem + SMEM_REC_OFF + (uint32_t)(pos * KK) * 16u;

            #pragma unroll
            for (int kb3 = 0; kb3 < 3; ++kb3) {
                uint4 rv[3];
                #pragma unroll
                for (int t = 0; t < 3; ++t)
                    rv[t] = *(const uint4*)(recp + (kb3 * 3 + t) * 16);

                float va[3][4], vb[3][4];
                #pragma unroll
                for (int t = 0; t < 3; ++t) {
                    const int j0 = (int)rv[t].x + lane;
                    const int dx = (int)(rv[t].y & 0xFFFFu);
                    const int dy = (int)(rv[t].y >> 16);
                    const int j1 = j0 + dx;
                    const int j2 = j0 + dy;
                    const int j3 = j1 + dy;
                    va[t][0] = __ldg(x + j0);
                    va[t][1] = __ldg(x + j1);
                    va[t][2] = __ldg(x + j2);
                    va[t][3] = __ldg(x + j3);
                    vb[t][0] = __ldg(x + Bstride + j0);
                    vb[t][1] = __ldg(x + Bstride + j1);
                    vb[t][2] = __ldg(x + Bstride + j2);
                    vb[t][3] = __ldg(x + Bstride + j3);
                }
                #pragma unroll
                for (int t = 0; t < 3; ++t) {
                    const int k = kb3 * 3 + t;
                    const float2 wA = __half22float2(*(const __half2*)&rv[t].z);
                    const float2 wB = __half22float2(*(const __half2*)&rv[t].w);
                    float s0 = wA.x * va[t][0];
                    s0 = fmaf(wA.y, va[t][1], s0);
                    s0 = fmaf(wB.x, va[t][2], s0);
                    s0 = fmaf(wB.y, va[t][3], s0);
                    float s1 = wA.x * vb[t][0];
                    s1 = fmaf(wA.y, vb[t][1], s1);
                    s1 = fmaf(wB.x, vb[t][2], s1);
                    s1 = fmaf(wB.y, vb[t][3], s1);

                    const uint32_t a0 = base0 + (uint32_t)k * 128u;
                    *(uint32_t*)(smem + a0) = hilo_f16(s0);
                    *(uint32_t*)(smem + a0 + ROW1_DELTA) = hilo_f16(s1);
                }
            }
        }
    }

    __syncthreads();

    // ---- Phase 3: HMMA GEMM. 8 warps: (rg = w&3 -> rows 16rg, nh = w>>2 -> n 16nh) ----
    if (w < 8) {
        const int rg = w & 3;
        const int nh = w >> 2;
        const int rowbase = rg * 16;

        const int rl  = rowbase + (lane & 7) + (lane & 8);               // A row
        const int kha = (lane >> 4) & 1;                                 // A k-half
        const int nr  = nh * 16 + (lane & 7) + (((lane >> 4) & 1) << 3); // B row
        const int khb = (lane >> 3) & 1;                                 // B k-half

        const uint32_t a_row = sbase + SMEM_A_OFF + (uint32_t)rl * ROWB;
        const uint32_t b_row = sbase + SMEM_B_OFF + (uint32_t)nr * ROWB;
        const uint32_t amask = (uint32_t)rl & 7u;
        const uint32_t bmask = (uint32_t)nr & 7u;

        float d[8];
        #pragma unroll
        for (int i = 0; i < 8; ++i) d[i] = 0.f;

        #pragma unroll 4
        for (int s = 0; s < 36; ++s) {
            const uint32_t grp = (uint32_t)(s >> 2) * 128u;
            const uint32_t s2  = (uint32_t)(2 * s);

            uint32_t a0, a1, a2, a3;
            LDMATRIX_X4(a0, a1, a2, a3,
                        a_row + grp + ((((s2 + (uint32_t)kha) & 7u) ^ amask) << 4));
            uint32_t b0, b1, b2, b3;
            LDMATRIX_X4(b0, b1, b2, b3,
                        b_row + grp + ((((s2 + (uint32_t)khb) & 7u) ^ bmask) << 4));

            MMA16816(d + 0, a0, a1, a2, a3, b0, b1);   // n 16nh+0..7
            MMA16816(d + 4, a0, a1, a2, a3, b2, b3);   // n 16nh+8..15
        }

        // ---- Epilogue ----
        const int g = lane >> 2;
        const int t = lane & 3;
        const int R0 = rowbase + g;
        const int R1 = R0 + 8;
        const int b0r = R0 >> 5, p0r = R0 & 31;
        const int b1r = R1 >> 5, p1r = R1 & 31;
        float* o0 = out + ((size_t)(b0r * HH + y) * WW + xbase + p0r) * FF + nh * 16;
        float* o1 = out + ((size_t)(b1r * HH + y) * WW + xbase + p1r) * FF + nh * 16;

        #pragma unroll
        for (int nt = 0; nt < 2; ++nt) {
            const int f0 = nt * 8 + 2 * t;
            const float2 bv = __ldg((const float2*)(bias + nh * 16 + f0));
            float2 v0 = make_float2(d[nt * 4 + 0] + bv.x, d[nt * 4 + 1] + bv.y);
            float2 v1 = make_float2(d[nt * 4 + 2] + bv.x, d[nt * 4 + 3] + bv.y);
            *(float2*)(o0 + f0) = v0;
            *(float2*)(o1 + f0) = v1;
        }
    }
}

extern "C" void kernel_launch(void* const* d_in, const int* in_sizes, int n_in,
                              void* d_out, int out_size)
{
    (void)in_sizes; (void)n_in; (void)out_size;
    const float* x    = (const float*)d_in[0];
    const float* off  = (const float*)d_in[1];
    const float* kern = (const float*)d_in[2];
    const float* bias = (const float*)d_in[3];
    float* out = (float*)d_out;

    cudaFuncSetAttribute(deform_conv_hmma,
                         cudaFuncAttributeMaxDynamicSharedMemorySize, SMEM_TOTAL);

    dim3 grid(WW / POS_PER_BLK, HH);
    deform_conv_hmma<<<grid, THREADS, SMEM_TOTAL>>>(x, off, kern, bias, out);
}

// round 8
// speedup vs baseline: 2.4946x; 1.2215x over previous
#include <cuda_runtime.h>
#include <cuda_fp16.h>
#include <cstdint>

#define HH 384
#define WW 384
#define CC 32
#define FF 32
#define KK 9
#define POS_PER_BLK 32
#define THREADS 512

// A: 64 rows x K'=576 fp16 (hi,lo interleaved) = 1152 B/row
#define ROWB 1152u
#define SMEM_A_OFF 0u
#define A_BYTES (64u * ROWB)                   // 73728
#define ROW1_DELTA (32u * ROWB)                // batch-1 row offset within A
// B: 32 rows x 576 (w,w) fp16 = 1152 B/row (duplicated along K')
#define SMEM_B_OFF A_BYTES                     // 73728
#define B_BYTES (32u * ROWB)                   // 36864
#define SMEM_REC_OFF (SMEM_B_OFF + B_BYTES)    // 110592
#define REC_BYTES (288u * 16u)                 // 4608
#define SMEM_TOTAL (SMEM_REC_OFF + REC_BYTES)  // 115200

// Pre-swizzled B tile image, built once per launch by prep kernel
__device__ uint4 d_Btile[B_BYTES / 16];        // 2304 uint4

__device__ __forceinline__ uint32_t smem_u32(const void* p) {
    uint32_t a;
    asm("{ .reg .u64 t; cvta.to.shared.u64 t, %1; cvt.u32.u64 %0, t; }" : "=r"(a) : "l"(p));
    return a;
}

#define LDMATRIX_X4(r0, r1, r2, r3, addr)                                   \
    asm volatile("ldmatrix.sync.aligned.m8n8.x4.shared.b16 {%0,%1,%2,%3}, [%4];" \
                 : "=r"(r0), "=r"(r1), "=r"(r2), "=r"(r3) : "r"(addr))

#define MMA16816(d, a0, a1, a2, a3, b0, b1)                                 \
    asm volatile("mma.sync.aligned.m16n8k16.row.col.f32.f16.f16.f32 "       \
                 "{%0,%1,%2,%3}, {%4,%5,%6,%7}, {%8,%9}, {%0,%1,%2,%3};"    \
                 : "+f"((d)[0]), "+f"((d)[1]), "+f"((d)[2]), "+f"((d)[3])   \
                 : "r"(a0), "r"(a1), "r"(a2), "r"(a3), "r"(b0), "r"(b1))

// fp32 -> packed (fp16 hi in low half | fp16 lo in high half)
__device__ __forceinline__ uint32_t hilo_f16(float s) {
    __half h = __float2half_rn(s);
    float l = s - __half2float(h);
    uint32_t r;
    asm("cvt.rn.f16x2.f32 %0, %1, %2;" : "=r"(r) : "f"(l), "f"(s));
    return r;
}

// ---- one-time B prep: swizzled (w,w) fp16 tile ----
__global__ void prep_b_kernel(const float* __restrict__ kern) {
    const int i = blockIdx.x * blockDim.x + threadIdx.x;
    if (i >= KK * CC * FF) return;
    const int f = i & 31;
    const int c = (i >> 5) & 31;
    const int k = i >> 10;
    const __half wh = __float2half_rn(__ldg(kern + (k * 32 + c) * 32 + f));
    const __half2 p = __halves2half2(wh, wh);
    const uint32_t addr = (uint32_t)f * ROWB + (uint32_t)k * 128u +
                          ((((uint32_t)(c >> 2)) ^ ((uint32_t)f & 7u)) << 4) +
                          ((uint32_t)(c & 3)) * 4u;
    ((uint32_t*)d_Btile)[addr >> 2] = *(const uint32_t*)&p;
}

extern __shared__ char smem[];

__global__ __launch_bounds__(THREADS, 2)
void deform_conv_hmma(const float* __restrict__ x,
                      const float* __restrict__ off,
                      const float* __restrict__ bias,
                      float* __restrict__ out)
{
    const uint32_t sbase = smem_u32(smem);
    const int tid  = threadIdx.x;
    const int lane = tid & 31;
    const int w    = tid >> 5;            // 16 warps
    const int y    = blockIdx.y;
    const int xbase = blockIdx.x * POS_PER_BLK;

    // ---- B fill: straight uint4 copy of pre-swizzled tile ----
    #pragma unroll
    for (int i = tid; i < (int)(B_BYTES / 16); i += THREADS)
        *((uint4*)(smem + SMEM_B_OFF) + i) = d_Btile[i];

    // ---- Stage 1: per-tap 16B records (ONE thread per tap) ----
    // rec = { i00_bytes, dx_b | dy_b<<16, (w00,w01) f16x2, (w10,w11) f16x2 }
    if (tid < POS_PER_BLK * KK) {
        const int j = tid;
        const int pos = j / KK;
        const int k   = j - pos * KK;
        const int xcol = xbase + pos;
        const float2 o = __ldg((const float2*)(off + (size_t)(y * WW + xcol) * (KK * 2) + 2 * k));

        // padded coords: tap base (y + k/3, x + k%3), pad=1, clamp to [0,385]
        float yf = fminf(fmaxf((float)(y + k / 3) + o.y, 0.f), 385.f);
        float xf = fminf(fmaxf((float)(xcol + k % 3) + o.x, 0.f), 385.f);
        const float y0f = floorf(yf), x0f = floorf(xf);
        const int y0 = (int)y0f, x0 = (int)x0f;
        const int y1 = min(y0 + 1, 385), x1 = min(x0 + 1, 385);
        const float wy0 = (float)y1 - yf, wy1 = yf - y0f;
        const float wx0 = (float)x1 - xf, wx1 = xf - x0f;

        const bool vy0 = (y0 >= 1) && (y0 <= 384);
        const bool vy1 = (y1 >= 1) && (y1 <= 384);
        const bool vx0 = (x0 >= 1) && (x0 <= 384);
        const bool vx1 = (x1 >= 1) && (x1 <= 384);
        const float w00 = (vy0 && vx0) ? wy0 * wx0 : 0.f;
        const float w01 = (vy0 && vx1) ? wy0 * wx1 : 0.f;
        const float w10 = (vy1 && vx0) ? wy1 * wx0 : 0.f;
        const float w11 = (vy1 && vx1) ? wy1 * wx1 : 0.f;

        const int y0c = min(max(y0, 1), 384), y1c = min(max(y1, 1), 384);
        const int x0c = min(max(x0, 1), 384), x1c = min(max(x1, 1), 384);
        const uint32_t i00b = (uint32_t)(((y0c - 1) * WW + (x0c - 1)) * CC) * 4u;
        const uint32_t dxb = (uint32_t)((x1c - x0c) * CC) * 4u;        // 0 or 128
        const uint32_t dyb = (uint32_t)((y1c - y0c) * WW * CC) * 4u;   // 0 or 49152

        const __half2 wA = __floats2half2_rn(w00, w01);
        const __half2 wB = __floats2half2_rn(w10, w11);
        uint4 rec;
        rec.x = i00b;
        rec.y = dxb | (dyb << 16);
        rec.z = *(const uint32_t*)&wA;
        rec.w = *(const uint32_t*)&wB;
        *(uint4*)(smem + SMEM_REC_OFF + (uint32_t)j * 16u) = rec;
    }

    __syncthreads();

    // ---- Stage 2: gather + blend -> interleaved split-fp16 A tile ----
    const char* xb0 = (const char*)x + (uint32_t)lane * 4u;
    const char* xb1 = xb0 + (size_t)HH * WW * CC * 4u;
    {
        const uint32_t swz = ((((uint32_t)lane >> 2)) << 4);
        #pragma unroll
        for (int p = 0; p < 2; ++p) {
            const int pos = w * 2 + p;
            const uint32_t base0 = SMEM_A_OFF + (uint32_t)pos * ROWB +
                                   (swz ^ (((uint32_t)pos & 7u) << 4)) +
                                   ((uint32_t)lane & 3u) * 4u;
            const char* recp = smem + SMEM_REC_OFF + (uint32_t)(pos * KK) * 16u;

            #pragma unroll
            for (int kb3 = 0; kb3 < 3; ++kb3) {
                uint4 rv[3];
                #pragma unroll
                for (int t = 0; t < 3; ++t)
                    rv[t] = *(const uint4*)(recp + (kb3 * 3 + t) * 16);

                float va[3][4], vb[3][4];
                #pragma unroll
                for (int t = 0; t < 3; ++t) {
                    const uint32_t dxb = rv[t].y & 0xFFFFu;
                    const uint32_t dyb = rv[t].y >> 16;
                    const uint32_t o0 = rv[t].x;
                    const uint32_t o1 = o0 + dxb;
                    const uint32_t o2 = o0 + dyb;
                    const uint32_t o3 = o1 + dyb;
                    va[t][0] = __ldg((const float*)(xb0 + o0));
                    va[t][1] = __ldg((const float*)(xb0 + o1));
                    va[t][2] = __ldg((const float*)(xb0 + o2));
                    va[t][3] = __ldg((const float*)(xb0 + o3));
                    vb[t][0] = __ldg((const float*)(xb1 + o0));
                    vb[t][1] = __ldg((const float*)(xb1 + o1));
                    vb[t][2] = __ldg((const float*)(xb1 + o2));
                    vb[t][3] = __ldg((const float*)(xb1 + o3));
                }
                #pragma unroll
                for (int t = 0; t < 3; ++t) {
                    const int k = kb3 * 3 + t;
                    const float2 wA = __half22float2(*(const __half2*)&rv[t].z);
                    const float2 wB = __half22float2(*(const __half2*)&rv[t].w);
                    float s0 = wA.x * va[t][0];
                    s0 = fmaf(wA.y, va[t][1], s0);
                    s0 = fmaf(wB.x, va[t][2], s0);
                    s0 = fmaf(wB.y, va[t][3], s0);
                    float s1 = wA.x * vb[t][0];
                    s1 = fmaf(wA.y, vb[t][1], s1);
                    s1 = fmaf(wB.x, vb[t][2], s1);
                    s1 = fmaf(wB.y, vb[t][3], s1);

                    const uint32_t a0 = base0 + (uint32_t)k * 128u;
                    *(uint32_t*)(smem + a0) = hilo_f16(s0);
                    *(uint32_t*)(smem + a0 + ROW1_DELTA) = hilo_f16(s1);
                }
            }
        }
    }

    __syncthreads();

    // ---- Phase 3: HMMA GEMM. 8 warps: (rg = w&3 -> rows 16rg, nh = w>>2 -> n 16nh) ----
    if (w < 8) {
        const int rg = w & 3;
        const int nh = w >> 2;
        const int rowbase = rg * 16;

        const int rl  = rowbase + (lane & 7) + (lane & 8);               // A row
        const int kha = (lane >> 4) & 1;                                 // A k-half
        const int nr  = nh * 16 + (lane & 7) + (((lane >> 4) & 1) << 3); // B row
        const int khb = (lane >> 3) & 1;                                 // B k-half

        // per-group-constant swizzled sub-offsets: step i in group -> ((2i+kh)&7 ^ mask)<<4
        uint32_t aoff[4], boff[4];
        #pragma unroll
        for (int i = 0; i < 4; ++i) {
            aoff[i] = ((((uint32_t)(2 * i + kha)) & 7u) ^ ((uint32_t)rl & 7u)) << 4;
            boff[i] = ((((uint32_t)(2 * i + khb)) & 7u) ^ ((uint32_t)nr & 7u)) << 4;
        }
        uint32_t a_base = sbase + SMEM_A_OFF + (uint32_t)rl * ROWB;
        uint32_t b_base = sbase + SMEM_B_OFF + (uint32_t)nr * ROWB;

        float d[8];
        #pragma unroll
        for (int i = 0; i < 8; ++i) d[i] = 0.f;

        #pragma unroll 3
        for (int g = 0; g < 9; ++g) {
            #pragma unroll
            for (int i = 0; i < 4; ++i) {
                uint32_t a0, a1, a2, a3;
                LDMATRIX_X4(a0, a1, a2, a3, a_base + aoff[i]);
                uint32_t b0, b1, b2, b3;
                LDMATRIX_X4(b0, b1, b2, b3, b_base + boff[i]);
                MMA16816(d + 0, a0, a1, a2, a3, b0, b1);
                MMA16816(d + 4, a0, a1, a2, a3, b2, b3);
            }
            a_base += 128u;
            b_base += 128u;
        }

        // ---- Epilogue ----
        const int g = lane >> 2;
        const int t = lane & 3;
        const int R0 = rowbase + g;
        const int R1 = R0 + 8;
        const int b0r = R0 >> 5, p0r = R0 & 31;
        const int b1r = R1 >> 5, p1r = R1 & 31;
        float* o0 = out + ((size_t)(b0r * HH + y) * WW + xbase + p0r) * FF + nh * 16;
        float* o1 = out + ((size_t)(b1r * HH + y) * WW + xbase + p1r) * FF + nh * 16;

        #pragma unroll
        for (int nt = 0; nt < 2; ++nt) {
            const int f0 = nt * 8 + 2 * t;
            const float2 bv = __ldg((const float2*)(bias + nh * 16 + f0));
            float2 v0 = make_float2(d[nt * 4 + 0] + bv.x, d[nt * 4 + 1] + bv.y);
            float2 v1 = make_float2(d[nt * 4 + 2] + bv.x, d[nt * 4 + 3] + bv.y);
            *(float2*)(o0 + f0) = v0;
            *(float2*)(o1 + f0) = v1;
        }
    }
}

extern "C" void kernel_launch(void* const* d_in, const int* in_sizes, int n_in,
                              void* d_out, int out_size)
{
    (void)in_sizes; (void)n_in; (void)out_size;
    const float* x    = (const float*)d_in[0];
    const float* off  = (const float*)d_in[1];
    const float* kern = (const float*)d_in[2];
    const float* bias = (const float*)d_in[3];
    float* out = (float*)d_out;

    prep_b_kernel<<<(KK * CC * FF + 255) / 256, 256>>>(kern);

    cudaFuncSetAttribute(deform_conv_hmma,
                         cudaFuncAttributeMaxDynamicSharedMemorySize, SMEM_TOTAL);

    dim3 grid(WW / POS_PER_BLK, HH);
    deform_conv_hmma<<<grid, THREADS, SMEM_TOTAL>>>(x, off, bias, out);
}

// round 9
// speedup vs baseline: 3.2398x; 1.2987x over previous
#include <cuda_runtime.h>
#include <cuda_fp16.h>
#include <cstdint>

#define HH 384
#define WW 384
#define CC 32
#define FF 32
#define KK 9
#define POS_PER_BLK 64
#define THREADS 512

// A: 128 rows x 288 fp16, row padded to 640 B (bank-aligned, 5 x 128B swizzle groups)
#define ROWB 640u
#define SMEM_A_OFF 0u
#define A_BYTES (128u * ROWB)                  // 81920
#define ROW1_DELTA (64u * ROWB)                // batch-1 row offset
// B: 32 rows x 288 fp16, row 640 B
#define SMEM_B_OFF A_BYTES                     // 81920
#define B_BYTES (32u * ROWB)                   // 20480
#define SMEM_REC_OFF (SMEM_B_OFF + B_BYTES)    // 102400
#define REC_BYTES (576u * 16u)                 // 9216
#define SMEM_TOTAL (SMEM_REC_OFF + REC_BYTES)  // 111616  (2 CTAs/SM)

// Pre-swizzled fp16 B tile, built once per launch
__device__ __align__(16) char d_Btile[B_BYTES];

__device__ __forceinline__ uint32_t smem_u32(const void* p) {
    uint32_t a;
    asm("{ .reg .u64 t; cvta.to.shared.u64 t, %1; cvt.u32.u64 %0, t; }" : "=r"(a) : "l"(p));
    return a;
}

#define LDMATRIX_X4(r0, r1, r2, r3, addr)                                   \
    asm volatile("ldmatrix.sync.aligned.m8n8.x4.shared.b16 {%0,%1,%2,%3}, [%4];" \
                 : "=r"(r0), "=r"(r1), "=r"(r2), "=r"(r3) : "r"(addr))

#define MMA16816(d, a0, a1, a2, a3, b0, b1)                                 \
    asm volatile("mma.sync.aligned.m16n8k16.row.col.f32.f16.f16.f32 "       \
                 "{%0,%1,%2,%3}, {%4,%5,%6,%7}, {%8,%9}, {%0,%1,%2,%3};"    \
                 : "+f"((d)[0]), "+f"((d)[1]), "+f"((d)[2]), "+f"((d)[3])   \
                 : "r"(a0), "r"(a1), "r"(a2), "r"(a3), "r"(b0), "r"(b1))

// swizzled byte address within a row for fp16 column kc (kb = kc*2), row mask rm = row&7
__device__ __forceinline__ uint32_t swz_addr(uint32_t kb, uint32_t rm) {
    return (kb & ~127u) + ((((kb >> 4) & 7u) ^ rm) << 4) + (kb & 15u);
}

// ---- one-time B prep: swizzled fp16 tile B[f][kc], kc = k*32 + c ----
__global__ void prep_b_kernel(const float* __restrict__ kern) {
    const int i = blockIdx.x * blockDim.x + threadIdx.x;
    if (i >= KK * CC * FF) return;
    const int f = i & 31;
    const int c = (i >> 5) & 31;
    const int k = i >> 10;
    const __half wh = __float2half_rn(__ldg(kern + (k * 32 + c) * 32 + f));
    const uint32_t kb = (uint32_t)(k * 64 + c * 2);
    *(__half*)(d_Btile + (uint32_t)f * ROWB + swz_addr(kb, (uint32_t)f & 7u)) = wh;
}

extern __shared__ char smem[];

__global__ __launch_bounds__(THREADS, 2)
void deform_conv_hmma(const float* __restrict__ x,
                      const float* __restrict__ off,
                      const float* __restrict__ bias,
                      float* __restrict__ out)
{
    const uint32_t sbase = smem_u32(smem);
    const int tid  = threadIdx.x;
    const int lane = tid & 31;
    const int w    = tid >> 5;            // 16 warps
    const int y    = blockIdx.y;
    const int xbase = blockIdx.x * POS_PER_BLK;

    // ---- B fill: straight uint4 copy ----
    #pragma unroll
    for (int i = tid; i < (int)(B_BYTES / 16); i += THREADS)
        ((uint4*)(smem + SMEM_B_OFF))[i] = ((const uint4*)d_Btile)[i];

    // ---- Stage 1: per-tap 16B records (one thread per tap; 576 taps) ----
    // rec = { i00_bytes, dx_b | dy_b<<16, (w00,w01) f16x2, (w10,w11) f16x2 }
    #pragma unroll
    for (int j = tid; j < POS_PER_BLK * KK; j += THREADS) {
        const int pos = j / KK;
        const int k   = j - pos * KK;
        const int xcol = xbase + pos;
        const float2 o = __ldg((const float2*)(off + (size_t)(y * WW + xcol) * (KK * 2) + 2 * k));

        // padded coords: tap base (y + k/3, x + k%3), pad=1, clamp to [0,385]
        float yf = fminf(fmaxf((float)(y + k / 3) + o.y, 0.f), 385.f);
        float xf = fminf(fmaxf((float)(xcol + k % 3) + o.x, 0.f), 385.f);
        const float y0f = floorf(yf), x0f = floorf(xf);
        const int y0 = (int)y0f, x0 = (int)x0f;
        const int y1 = min(y0 + 1, 385), x1 = min(x0 + 1, 385);
        const float wy0 = (float)y1 - yf, wy1 = yf - y0f;
        const float wx0 = (float)x1 - xf, wx1 = xf - x0f;

        const bool vy0 = (y0 >= 1) && (y0 <= 384);
        const bool vy1 = (y1 >= 1) && (y1 <= 384);
        const bool vx0 = (x0 >= 1) && (x0 <= 384);
        const bool vx1 = (x1 >= 1) && (x1 <= 384);
        const float w00 = (vy0 && vx0) ? wy0 * wx0 : 0.f;
        const float w01 = (vy0 && vx1) ? wy0 * wx1 : 0.f;
        const float w10 = (vy1 && vx0) ? wy1 * wx0 : 0.f;
        const float w11 = (vy1 && vx1) ? wy1 * wx1 : 0.f;

        const int y0c = min(max(y0, 1), 384), y1c = min(max(y1, 1), 384);
        const int x0c = min(max(x0, 1), 384), x1c = min(max(x1, 1), 384);
        const uint32_t i00b = (uint32_t)(((y0c - 1) * WW + (x0c - 1)) * CC) * 4u;
        const uint32_t dxb = (uint32_t)((x1c - x0c) * CC) * 4u;        // 0 or 128
        const uint32_t dyb = (uint32_t)((y1c - y0c) * WW * CC) * 4u;   // 0 or 49152

        const __half2 wA = __floats2half2_rn(w00, w01);
        const __half2 wB = __floats2half2_rn(w10, w11);
        uint4 rec;
        rec.x = i00b;
        rec.y = dxb | (dyb << 16);
        rec.z = *(const uint32_t*)&wA;
        rec.w = *(const uint32_t*)&wB;
        *(uint4*)(smem + SMEM_REC_OFF + (uint32_t)j * 16u) = rec;
    }

    __syncthreads();

    // ---- Stage 2: gather + blend -> fp16 A tile ----
    // warp w owns positions 4w..4w+3; lane = channel c. Store: STS.16 per (tap,batch).
    const char* xb0 = (const char*)x + (uint32_t)lane * 4u;
    const char* xb1 = xb0 + (size_t)HH * WW * CC * 4u;
    {
        const uint32_t lane2 = (uint32_t)lane * 2u;
        const uint32_t l3    = (uint32_t)lane >> 3;
        #pragma unroll
        for (int p = 0; p < 4; ++p) {
            const int pos = w * 4 + p;
            const uint32_t rm = (uint32_t)pos & 7u;
            const uint32_t rowb = SMEM_A_OFF + (uint32_t)pos * ROWB + (lane2 & 15u);
            const char* recp = smem + SMEM_REC_OFF + (uint32_t)(pos * KK) * 16u;

            #pragma unroll
            for (int kb3 = 0; kb3 < 3; ++kb3) {
                uint4 rv[3];
                #pragma unroll
                for (int t = 0; t < 3; ++t)
                    rv[t] = *(const uint4*)(recp + (kb3 * 3 + t) * 16);

                float va[3][4], vb[3][4];
                #pragma unroll
                for (int t = 0; t < 3; ++t) {
                    const uint32_t dxb = rv[t].y & 0xFFFFu;
                    const uint32_t dyb = rv[t].y >> 16;
                    const uint32_t o0 = rv[t].x;
                    const uint32_t o1 = o0 + dxb;
                    const uint32_t o2 = o0 + dyb;
                    const uint32_t o3 = o1 + dyb;
                    va[t][0] = __ldg((const float*)(xb0 + o0));
                    va[t][1] = __ldg((const float*)(xb0 + o1));
                    va[t][2] = __ldg((const float*)(xb0 + o2));
                    va[t][3] = __ldg((const float*)(xb0 + o3));
                    vb[t][0] = __ldg((const float*)(xb1 + o0));
                    vb[t][1] = __ldg((const float*)(xb1 + o1));
                    vb[t][2] = __ldg((const float*)(xb1 + o2));
                    vb[t][3] = __ldg((const float*)(xb1 + o3));
                }
                #pragma unroll
                for (int t = 0; t < 3; ++t) {
                    const int k = kb3 * 3 + t;
                    const float2 wA = __half22float2(*(const __half2*)&rv[t].z);
                    const float2 wB = __half22float2(*(const __half2*)&rv[t].w);
                    float s0 = wA.x * va[t][0];
                    s0 = fmaf(wA.y, va[t][1], s0);
                    s0 = fmaf(wB.x, va[t][2], s0);
                    s0 = fmaf(wB.y, va[t][3], s0);
                    float s1 = wA.x * vb[t][0];
                    s1 = fmaf(wA.y, vb[t][1], s1);
                    s1 = fmaf(wB.x, vb[t][2], s1);
                    s1 = fmaf(wB.y, vb[t][3], s1);

                    // kb = k*64 + lane*2; addr = row + group + (block ^ rm)<<4 + low
                    const uint32_t kb = (uint32_t)k * 64u + lane2;
                    const uint32_t addr = rowb + (kb & ~127u) +
                                          ((((4u * (uint32_t)k + l3) & 7u) ^ rm) << 4);
                    *(__half*)(smem + addr) = __float2half_rn(s0);
                    *(__half*)(smem + addr + ROW1_DELTA) = __float2half_rn(s1);
                }
            }
        }
    }

    __syncthreads();

    // ---- Phase 3: HMMA GEMM. 8 warps: warp w -> rows 16w..16w+15, all N=32 ----
    if (w < 8) {
        const int rowbase = w * 16;

        const int rl  = rowbase + (lane & 7) + (lane & 8);               // A row
        const int kha = (lane >> 4) & 1;                                 // A k-half
        const int nr  = (lane & 7) + (((lane >> 4) & 1) << 3);           // B row (n 0..15)
        const int khb = (lane >> 3) & 1;                                 // B k-half

        uint32_t aoff[4], boff[4];
        #pragma unroll
        for (int i = 0; i < 4; ++i) {
            aoff[i] = ((((uint32_t)(2 * i + kha)) & 7u) ^ ((uint32_t)rl & 7u)) << 4;
            boff[i] = ((((uint32_t)(2 * i + khb)) & 7u) ^ ((uint32_t)nr & 7u)) << 4;
        }
        uint32_t a_base  = sbase + SMEM_A_OFF + (uint32_t)rl * ROWB;
        uint32_t b_base0 = sbase + SMEM_B_OFF + (uint32_t)nr * ROWB;
        uint32_t b_base1 = b_base0 + 16u * ROWB;                          // n 16..31

        float d[16];
        #pragma unroll
        for (int i = 0; i < 16; ++i) d[i] = 0.f;

        // 18 K-steps = 4 groups of 4 + 1 group of 2
        #pragma unroll
        for (int g = 0; g < 5; ++g) {
            const int steps = (g < 4) ? 4 : 2;
            #pragma unroll
            for (int i = 0; i < 4; ++i) {
                if (i >= steps) break;
                uint32_t a0, a1, a2, a3;
                LDMATRIX_X4(a0, a1, a2, a3, a_base + aoff[i]);
                uint32_t b0, b1, b2, b3;
                LDMATRIX_X4(b0, b1, b2, b3, b_base0 + boff[i]);
                uint32_t b4, b5, b6, b7;
                LDMATRIX_X4(b4, b5, b6, b7, b_base1 + boff[i]);
                MMA16816(d + 0,  a0, a1, a2, a3, b0, b1);   // n 0..7
                MMA16816(d + 4,  a0, a1, a2, a3, b2, b3);   // n 8..15
                MMA16816(d + 8,  a0, a1, a2, a3, b4, b5);   // n 16..23
                MMA16816(d + 12, a0, a1, a2, a3, b6, b7);   // n 24..31
            }
            a_base  += 128u;
            b_base0 += 128u;
            b_base1 += 128u;
        }

        // ---- Epilogue ----
        const int g = lane >> 2;
        const int t = lane & 3;
        const int R0 = rowbase + g;
        const int R1 = R0 + 8;
        const int b0r = R0 >> 6, p0r = R0 & 63;
        const int b1r = R1 >> 6, p1r = R1 & 63;
        float* o0 = out + ((size_t)(b0r * HH + y) * WW + xbase + p0r) * FF;
        float* o1 = out + ((size_t)(b1r * HH + y) * WW + xbase + p1r) * FF;

        #pragma unroll
        for (int nt = 0; nt < 4; ++nt) {
            const int f0 = nt * 8 + 2 * t;
            const float2 bv = __ldg((const float2*)(bias + f0));
            float2 v0 = make_float2(d[nt * 4 + 0] + bv.x, d[nt * 4 + 1] + bv.y);
            float2 v1 = make_float2(d[nt * 4 + 2] + bv.x, d[nt * 4 + 3] + bv.y);
            *(float2*)(o0 + f0) = v0;
            *(float2*)(o1 + f0) = v1;
        }
    }
}

extern "C" void kernel_launch(void* const* d_in, const int* in_sizes, int n_in,
                              void* d_out, int out_size)
{
    (void)in_sizes; (void)n_in; (void)out_size;
    const float* x    = (const float*)d_in[0];
    const float* off  = (const float*)d_in[1];
    const float* kern = (const float*)d_in[2];
    const float* bias = (const float*)d_in[3];
    float* out = (float*)d_out;

    prep_b_kernel<<<(KK * CC * FF + 255) / 256, 256>>>(kern);

    cudaFuncSetAttribute(deform_conv_hmma,
                         cudaFuncAttributeMaxDynamicSharedMemorySize, SMEM_TOTAL);

    dim3 grid(WW / POS_PER_BLK, HH);
    deform_conv_hmma<<<grid, THREADS, SMEM_TOTAL>>>(x, off, bias, out);
}

// round 10
// speedup vs baseline: 3.3232x; 1.0258x over previous
#include <cuda_runtime.h>
#include <cuda_fp16.h>
#include <cstdint>

#define HH 384
#define WW 384
#define CC 32
#define FF 32
#define KK 9
#define POS_PER_BLK 64
#define THREADS 512

// A: 128 rows x 288 fp16, row padded to 640 B
#define ROWB 640u
#define SMEM_A_OFF 0u
#define A_BYTES (128u * ROWB)                  // 81920
#define ROW1_DELTA (64u * ROWB)                // batch-1 row offset
// B: 32 rows x 288 fp16, row 640 B
#define SMEM_B_OFF A_BYTES                     // 81920
#define B_BYTES (32u * ROWB)                   // 20480
#define SMEM_REC_OFF (SMEM_B_OFF + B_BYTES)    // 102400
#define REC_BYTES (576u * 16u)                 // 9216
#define SMEM_TOTAL (SMEM_REC_OFF + REC_BYTES)  // 111616  (2 CTAs/SM)

#define NPIXC (HH * WW * CC)

// Pre-swizzled fp16 B tile + batch-interleaved fp16 x image (built per launch)
__device__ __align__(16) char d_Btile[B_BYTES];
__device__ __align__(16) __half2 d_xh[NPIXC];   // [pix][c] = (x_b0, x_b1)

__device__ __forceinline__ uint32_t smem_u32(const void* p) {
    uint32_t a;
    asm("{ .reg .u64 t; cvta.to.shared.u64 t, %1; cvt.u32.u64 %0, t; }" : "=r"(a) : "l"(p));
    return a;
}

#define LDMATRIX_X4(r0, r1, r2, r3, addr)                                   \
    asm volatile("ldmatrix.sync.aligned.m8n8.x4.shared.b16 {%0,%1,%2,%3}, [%4];" \
                 : "=r"(r0), "=r"(r1), "=r"(r2), "=r"(r3) : "r"(addr))

#define MMA16816(d, a0, a1, a2, a3, b0, b1)                                 \
    asm volatile("mma.sync.aligned.m16n8k16.row.col.f32.f16.f16.f32 "       \
                 "{%0,%1,%2,%3}, {%4,%5,%6,%7}, {%8,%9}, {%0,%1,%2,%3};"    \
                 : "+f"((d)[0]), "+f"((d)[1]), "+f"((d)[2]), "+f"((d)[3])   \
                 : "r"(a0), "r"(a1), "r"(a2), "r"(a3), "r"(b0), "r"(b1))

__device__ __forceinline__ uint32_t swz_addr(uint32_t kb, uint32_t rm) {
    return (kb & ~127u) + ((((kb >> 4) & 7u) ^ rm) << 4) + (kb & 15u);
}

// ---- one-time preps ----
__global__ void prep_b_kernel(const float* __restrict__ kern) {
    const int i = blockIdx.x * blockDim.x + threadIdx.x;
    if (i >= KK * CC * FF) return;
    const int f = i & 31;
    const int c = (i >> 5) & 31;
    const int k = i >> 10;
    const __half wh = __float2half_rn(__ldg(kern + (k * 32 + c) * 32 + f));
    const uint32_t kb = (uint32_t)(k * 64 + c * 2);
    *(__half*)(d_Btile + (uint32_t)f * ROWB + swz_addr(kb, (uint32_t)f & 7u)) = wh;
}

__global__ void prep_x_kernel(const float* __restrict__ x) {
    const int i = blockIdx.x * blockDim.x + threadIdx.x;
    if (i >= NPIXC) return;
    d_xh[i] = __floats2half2_rn(__ldg(x + i), __ldg(x + NPIXC + i));
}

extern __shared__ char smem[];

__global__ __launch_bounds__(THREADS, 2)
void deform_conv_hmma(const float* __restrict__ off,
                      const float* __restrict__ bias,
                      float* __restrict__ out)
{
    const uint32_t sbase = smem_u32(smem);
    const int tid  = threadIdx.x;
    const int lane = tid & 31;
    const int w    = tid >> 5;            // 16 warps
    const int y    = blockIdx.y;
    const int xbase = blockIdx.x * POS_PER_BLK;

    // ---- B fill: straight uint4 copy ----
    #pragma unroll
    for (int i = tid; i < (int)(B_BYTES / 16); i += THREADS)
        ((uint4*)(smem + SMEM_B_OFF))[i] = ((const uint4*)d_Btile)[i];

    // ---- Stage 1: per-tap 16B records (one thread per tap; 576 taps) ----
    // rec = { i00_bytes, dx_b | dy_b<<16, (w00,w01) f16x2, (w10,w11) f16x2 }
    // NOTE: byte strides identical in fp32-x and half2-x images (128 B / pixel).
    #pragma unroll
    for (int j = tid; j < POS_PER_BLK * KK; j += THREADS) {
        const int pos = j / KK;
        const int k   = j - pos * KK;
        const int xcol = xbase + pos;
        const float2 o = __ldg((const float2*)(off + (size_t)(y * WW + xcol) * (KK * 2) + 2 * k));

        // padded coords: tap base (y + k/3, x + k%3), pad=1, clamp to [0,385]
        float yf = fminf(fmaxf((float)(y + k / 3) + o.y, 0.f), 385.f);
        float xf = fminf(fmaxf((float)(xcol + k % 3) + o.x, 0.f), 385.f);
        const float y0f = floorf(yf), x0f = floorf(xf);
        const int y0 = (int)y0f, x0 = (int)x0f;
        const int y1 = min(y0 + 1, 385), x1 = min(x0 + 1, 385);
        const float wy0 = (float)y1 - yf, wy1 = yf - y0f;
        const float wx0 = (float)x1 - xf, wx1 = xf - x0f;

        const bool vy0 = (y0 >= 1) && (y0 <= 384);
        const bool vy1 = (y1 >= 1) && (y1 <= 384);
        const bool vx0 = (x0 >= 1) && (x0 <= 384);
        const bool vx1 = (x1 >= 1) && (x1 <= 384);
        const float w00 = (vy0 && vx0) ? wy0 * wx0 : 0.f;
        const float w01 = (vy0 && vx1) ? wy0 * wx1 : 0.f;
        const float w10 = (vy1 && vx0) ? wy1 * wx0 : 0.f;
        const float w11 = (vy1 && vx1) ? wy1 * wx1 : 0.f;

        const int y0c = min(max(y0, 1), 384), y1c = min(max(y1, 1), 384);
        const int x0c = min(max(x0, 1), 384), x1c = min(max(x1, 1), 384);
        const uint32_t i00b = (uint32_t)(((y0c - 1) * WW + (x0c - 1)) * CC) * 4u;
        const uint32_t dxb = (uint32_t)((x1c - x0c) * CC) * 4u;        // 0 or 128
        const uint32_t dyb = (uint32_t)((y1c - y0c) * WW * CC) * 4u;   // 0 or 49152

        const __half2 wA = __floats2half2_rn(w00, w01);
        const __half2 wB = __floats2half2_rn(w10, w11);
        uint4 rec;
        rec.x = i00b;
        rec.y = dxb | (dyb << 16);
        rec.z = *(const uint32_t*)&wA;
        rec.w = *(const uint32_t*)&wB;
        *(uint4*)(smem + SMEM_REC_OFF + (uint32_t)j * 16u) = rec;
    }

    __syncthreads();

    // ---- Stage 2: gather (half2 = both batches) + fp32 blend -> fp16 A tile ----
    const char* xh = (const char*)d_xh + (uint32_t)lane * 4u;
    {
        const uint32_t lane2 = (uint32_t)lane * 2u;
        const uint32_t l3    = (uint32_t)lane >> 3;
        #pragma unroll
        for (int p = 0; p < 4; ++p) {
            const int pos = w * 4 + p;
            const uint32_t rm = (uint32_t)pos & 7u;
            const uint32_t rowb = SMEM_A_OFF + (uint32_t)pos * ROWB + (lane2 & 15u);
            const char* recp = smem + SMEM_REC_OFF + (uint32_t)(pos * KK) * 16u;

            #pragma unroll
            for (int kb3 = 0; kb3 < 3; ++kb3) {
                uint4 rv[3];
                #pragma unroll
                for (int t = 0; t < 3; ++t)
                    rv[t] = *(const uint4*)(recp + (kb3 * 3 + t) * 16);

                __half2 h[3][4];
                #pragma unroll
                for (int t = 0; t < 3; ++t) {
                    const uint32_t dxb = rv[t].y & 0xFFFFu;
                    const uint32_t dyb = rv[t].y >> 16;
                    const uint32_t o0 = rv[t].x;
                    const uint32_t o1 = o0 + dxb;
                    const uint32_t o2 = o0 + dyb;
                    const uint32_t o3 = o1 + dyb;
                    h[t][0] = __ldg((const __half2*)(xh + o0));
                    h[t][1] = __ldg((const __half2*)(xh + o1));
                    h[t][2] = __ldg((const __half2*)(xh + o2));
                    h[t][3] = __ldg((const __half2*)(xh + o3));
                }
                #pragma unroll
                for (int t = 0; t < 3; ++t) {
                    const int k = kb3 * 3 + t;
                    const float2 wA = __half22float2(*(const __half2*)&rv[t].z);
                    const float2 wB = __half22float2(*(const __half2*)&rv[t].w);
                    const float2 f0 = __half22float2(h[t][0]);
                    const float2 f1 = __half22float2(h[t][1]);
                    const float2 f2 = __half22float2(h[t][2]);
                    const float2 f3 = __half22float2(h[t][3]);
                    float s0 = wA.x * f0.x;
                    s0 = fmaf(wA.y, f1.x, s0);
                    s0 = fmaf(wB.x, f2.x, s0);
                    s0 = fmaf(wB.y, f3.x, s0);
                    float s1 = wA.x * f0.y;
                    s1 = fmaf(wA.y, f1.y, s1);
                    s1 = fmaf(wB.x, f2.y, s1);
                    s1 = fmaf(wB.y, f3.y, s1);

                    const uint32_t kb = (uint32_t)k * 64u + lane2;
                    const uint32_t addr = rowb + (kb & ~127u) +
                                          ((((4u * (uint32_t)k + l3) & 7u) ^ rm) << 4);
                    *(__half*)(smem + addr) = __float2half_rn(s0);
                    *(__half*)(smem + addr + ROW1_DELTA) = __float2half_rn(s1);
                }
            }
        }
    }

    __syncthreads();

    // ---- Phase 3: HMMA GEMM. 8 warps: warp w -> rows 16w..16w+15, all N=32 ----
    if (w < 8) {
        const int rowbase = w * 16;

        const int rl  = rowbase + (lane & 7) + (lane & 8);               // A row
        const int kha = (lane >> 4) & 1;                                 // A k-half
        const int nr  = (lane & 7) + (((lane >> 4) & 1) << 3);           // B row (n 0..15)
        const int khb = (lane >> 3) & 1;                                 // B k-half

        uint32_t aoff[4], boff[4];
        #pragma unroll
        for (int i = 0; i < 4; ++i) {
            aoff[i] = ((((uint32_t)(2 * i + kha)) & 7u) ^ ((uint32_t)rl & 7u)) << 4;
            boff[i] = ((((uint32_t)(2 * i + khb)) & 7u) ^ ((uint32_t)nr & 7u)) << 4;
        }
        uint32_t a_base  = sbase + SMEM_A_OFF + (uint32_t)rl * ROWB;
        uint32_t b_base0 = sbase + SMEM_B_OFF + (uint32_t)nr * ROWB;
        uint32_t b_base1 = b_base0 + 16u * ROWB;                          // n 16..31

        float d[16];
        #pragma unroll
        for (int i = 0; i < 16; ++i) d[i] = 0.f;

        // 18 K-steps = 4 groups of 4 + 1 group of 2
        #pragma unroll
        for (int g = 0; g < 5; ++g) {
            const int steps = (g < 4) ? 4 : 2;
            #pragma unroll
            for (int i = 0; i < 4; ++i) {
                if (i >= steps) break;
                uint32_t a0, a1, a2, a3;
                LDMATRIX_X4(a0, a1, a2, a3, a_base + aoff[i]);
                uint32_t b0, b1, b2, b3;
                LDMATRIX_X4(b0, b1, b2, b3, b_base0 + boff[i]);
                uint32_t b4, b5, b6, b7;
                LDMATRIX_X4(b4, b5, b6, b7, b_base1 + boff[i]);
                MMA16816(d + 0,  a0, a1, a2, a3, b0, b1);   // n 0..7
                MMA16816(d + 4,  a0, a1, a2, a3, b2, b3);   // n 8..15
                MMA16816(d + 8,  a0, a1, a2, a3, b4, b5);   // n 16..23
                MMA16816(d + 12, a0, a1, a2, a3, b6, b7);   // n 24..31
            }
            a_base  += 128u;
            b_base0 += 128u;
            b_base1 += 128u;
        }

        // ---- Epilogue ----
        const int g = lane >> 2;
        const int t = lane & 3;
        const int R0 = rowbase + g;
        const int R1 = R0 + 8;
        const int b0r = R0 >> 6, p0r = R0 & 63;
        const int b1r = R1 >> 6, p1r = R1 & 63;
        float* o0 = out + ((size_t)(b0r * HH + y) * WW + xbase + p0r) * FF;
        float* o1 = out + ((size_t)(b1r * HH + y) * WW + xbase + p1r) * FF;

        #pragma unroll
        for (int nt = 0; nt < 4; ++nt) {
            const int f0 = nt * 8 + 2 * t;
            const float2 bv = __ldg((const float2*)(bias + f0));
            float2 v0 = make_float2(d[nt * 4 + 0] + bv.x, d[nt * 4 + 1] + bv.y);
            float2 v1 = make_float2(d[nt * 4 + 2] + bv.x, d[nt * 4 + 3] + bv.y);
            *(float2*)(o0 + f0) = v0;
            *(float2*)(o1 + f0) = v1;
        }
    }
}

extern "C" void kernel_launch(void* const* d_in, const int* in_sizes, int n_in,
                              void* d_out, int out_size)
{
    (void)in_sizes; (void)n_in; (void)out_size;
    const float* x    = (const float*)d_in[0];
    const float* off  = (const float*)d_in[1];
    const float* kern = (const float*)d_in[2];
    const float* bias = (const float*)d_in[3];
    float* out = (float*)d_out;

    prep_b_kernel<<<(KK * CC * FF + 255) / 256, 256>>>(kern);
    prep_x_kernel<<<(NPIXC + 255) / 256, 256>>>(x);

    cudaFuncSetAttribute(deform_conv_hmma,
                         cudaFuncAttributeMaxDynamicSharedMemorySize, SMEM_TOTAL);

    dim3 grid(WW / POS_PER_BLK, HH);
    deform_conv_hmma<<<grid, THREADS, SMEM_TOTAL>>>(off, bias, out);
}

// round 11
// speedup vs baseline: 3.7204x; 1.1195x over previous
#include <cuda_runtime.h>
#include <cuda_fp16.h>
#include <cstdint>

#define HH 384
#define WW 384
#define CC 32
#define FF 32
#define KK 9
#define POS_PER_BLK 64
#define THREADS 512

// A: 128 rows x 288 fp16, row padded to 640 B
#define ROWB 640u
#define SMEM_A_OFF 0u
#define A_BYTES (128u * ROWB)                  // 81920
#define ROW1_DELTA (64u * ROWB)                // batch-1 row offset
// B: 32 rows x 288 fp16, row 640 B
#define SMEM_B_OFF A_BYTES                     // 81920
#define B_BYTES (32u * ROWB)                   // 20480
#define SMEM_REC_OFF (SMEM_B_OFF + B_BYTES)    // 102400
#define REC_BYTES (576u * 16u)                 // 9216
#define SMEM_TOTAL (SMEM_REC_OFF + REC_BYTES)  // 111616  (2 CTAs/SM)

#define NPIXC (HH * WW * CC)

// Pre-swizzled fp16 B tile + batch-interleaved fp16 x image (built per launch)
__device__ __align__(16) char d_Btile[B_BYTES];
__device__ __align__(16) __half2 d_xh[NPIXC];   // [pix][c] = (x_b0, x_b1)

__device__ __forceinline__ uint32_t smem_u32(const void* p) {
    uint32_t a;
    asm("{ .reg .u64 t; cvta.to.shared.u64 t, %1; cvt.u32.u64 %0, t; }" : "=r"(a) : "l"(p));
    return a;
}

#define LDMATRIX_X4(r0, r1, r2, r3, addr)                                   \
    asm volatile("ldmatrix.sync.aligned.m8n8.x4.shared.b16 {%0,%1,%2,%3}, [%4];" \
                 : "=r"(r0), "=r"(r1), "=r"(r2), "=r"(r3) : "r"(addr))

#define MMA16816(d, a0, a1, a2, a3, b0, b1)                                 \
    asm volatile("mma.sync.aligned.m16n8k16.row.col.f32.f16.f16.f32 "       \
                 "{%0,%1,%2,%3}, {%4,%5,%6,%7}, {%8,%9}, {%0,%1,%2,%3};"    \
                 : "+f"((d)[0]), "+f"((d)[1]), "+f"((d)[2]), "+f"((d)[3])   \
                 : "r"(a0), "r"(a1), "r"(a2), "r"(a3), "r"(b0), "r"(b1))

__device__ __forceinline__ uint32_t swz_addr(uint32_t kb, uint32_t rm) {
    return (kb & ~127u) + ((((kb >> 4) & 7u) ^ rm) << 4) + (kb & 15u);
}

// ---- one merged prep: half2 x image (vectorized) + swizzled fp16 B tile ----
__global__ void prep_kernel(const float* __restrict__ x, const float* __restrict__ kern) {
    const int i = blockIdx.x * blockDim.x + threadIdx.x;
    const int base = i * 4;
    if (base < NPIXC) {
        const float4 a = __ldg((const float4*)(x + base));
        const float4 b = __ldg((const float4*)(x + NPIXC + base));
        uint4 o;
        const __half2 h0 = __floats2half2_rn(a.x, b.x);
        const __half2 h1 = __floats2half2_rn(a.y, b.y);
        const __half2 h2 = __floats2half2_rn(a.z, b.z);
        const __half2 h3 = __floats2half2_rn(a.w, b.w);
        o.x = *(const uint32_t*)&h0;
        o.y = *(const uint32_t*)&h1;
        o.z = *(const uint32_t*)&h2;
        o.w = *(const uint32_t*)&h3;
        *(uint4*)(d_xh + base) = o;
    }
    if (i < KK * CC * FF) {
        const int f = i & 31;
        const int c = (i >> 5) & 31;
        const int k = i >> 10;
        const __half wh = __float2half_rn(__ldg(kern + (k * 32 + c) * 32 + f));
        const uint32_t kb = (uint32_t)(k * 64 + c * 2);
        *(__half*)(d_Btile + (uint32_t)f * ROWB + swz_addr(kb, (uint32_t)f & 7u)) = wh;
    }
}

extern __shared__ char smem[];

__global__ __launch_bounds__(THREADS, 2)
void deform_conv_hmma(const float* __restrict__ off,
                      const float* __restrict__ bias,
                      float* __restrict__ out)
{
    const uint32_t sbase = smem_u32(smem);
    const int tid  = threadIdx.x;
    const int lane = tid & 31;
    const int w    = tid >> 5;            // 16 warps
    const int y    = blockIdx.y;
    const int xbase = blockIdx.x * POS_PER_BLK;

    // ---- B fill: straight uint4 copy ----
    #pragma unroll
    for (int i = tid; i < (int)(B_BYTES / 16); i += THREADS)
        ((uint4*)(smem + SMEM_B_OFF))[i] = ((const uint4*)d_Btile)[i];

    // ---- Stage 1: per-tap 16B records (one thread per tap; 576 taps) ----
    #pragma unroll
    for (int j = tid; j < POS_PER_BLK * KK; j += THREADS) {
        const int pos = j / KK;
        const int k   = j - pos * KK;
        const int xcol = xbase + pos;
        const float2 o = __ldg((const float2*)(off + (size_t)(y * WW + xcol) * (KK * 2) + 2 * k));

        // padded coords: tap base (y + k/3, x + k%3), pad=1, clamp to [0,385]
        float yf = fminf(fmaxf((float)(y + k / 3) + o.y, 0.f), 385.f);
        float xf = fminf(fmaxf((float)(xcol + k % 3) + o.x, 0.f), 385.f);
        const float y0f = floorf(yf), x0f = floorf(xf);
        const int y0 = (int)y0f, x0 = (int)x0f;
        const int y1 = min(y0 + 1, 385), x1 = min(x0 + 1, 385);
        const float wy0 = (float)y1 - yf, wy1 = yf - y0f;
        const float wx0 = (float)x1 - xf, wx1 = xf - x0f;

        const bool vy0 = (y0 >= 1) && (y0 <= 384);
        const bool vy1 = (y1 >= 1) && (y1 <= 384);
        const bool vx0 = (x0 >= 1) && (x0 <= 384);
        const bool vx1 = (x1 >= 1) && (x1 <= 384);
        const float w00 = (vy0 && vx0) ? wy0 * wx0 : 0.f;
        const float w01 = (vy0 && vx1) ? wy0 * wx1 : 0.f;
        const float w10 = (vy1 && vx0) ? wy1 * wx0 : 0.f;
        const float w11 = (vy1 && vx1) ? wy1 * wx1 : 0.f;

        const int y0c = min(max(y0, 1), 384), y1c = min(max(y1, 1), 384);
        const int x0c = min(max(x0, 1), 384), x1c = min(max(x1, 1), 384);
        const uint32_t i00b = (uint32_t)(((y0c - 1) * WW + (x0c - 1)) * CC) * 4u;
        const uint32_t dxb = (uint32_t)((x1c - x0c) * CC) * 4u;        // 0 or 128
        const uint32_t dyb = (uint32_t)((y1c - y0c) * WW * CC) * 4u;   // 0 or 49152

        const __half2 wA = __floats2half2_rn(w00, w01);
        const __half2 wB = __floats2half2_rn(w10, w11);
        uint4 rec;
        rec.x = i00b;
        rec.y = dxb | (dyb << 16);
        rec.z = *(const uint32_t*)&wA;
        rec.w = *(const uint32_t*)&wB;
        *(uint4*)(smem + SMEM_REC_OFF + (uint32_t)j * 16u) = rec;
    }

    __syncthreads();

    // ---- Stage 2: gather (half2 = both batches) + fp32 blend -> fp16 A tile ----
    const char* xh = (const char*)d_xh + (uint32_t)lane * 4u;
    {
        const uint32_t lane2 = (uint32_t)lane * 2u;
        const uint32_t l3    = (uint32_t)lane >> 3;
        #pragma unroll
        for (int p = 0; p < 4; ++p) {
            const int pos = w * 4 + p;
            const uint32_t rm = (uint32_t)pos & 7u;
            const uint32_t rowb = SMEM_A_OFF + (uint32_t)pos * ROWB + (lane2 & 15u);
            const char* recp = smem + SMEM_REC_OFF + (uint32_t)(pos * KK) * 16u;

            #pragma unroll
            for (int kb3 = 0; kb3 < 3; ++kb3) {
                uint4 rv[3];
                #pragma unroll
                for (int t = 0; t < 3; ++t)
                    rv[t] = *(const uint4*)(recp + (kb3 * 3 + t) * 16);

                __half2 h[3][4];
                #pragma unroll
                for (int t = 0; t < 3; ++t) {
                    const uint32_t dxb = rv[t].y & 0xFFFFu;
                    const uint32_t dyb = rv[t].y >> 16;
                    const uint32_t o0 = rv[t].x;
                    const uint32_t o1 = o0 + dxb;
                    const uint32_t o2 = o0 + dyb;
                    const uint32_t o3 = o1 + dyb;
                    h[t][0] = __ldg((const __half2*)(xh + o0));
                    h[t][1] = __ldg((const __half2*)(xh + o1));
                    h[t][2] = __ldg((const __half2*)(xh + o2));
                    h[t][3] = __ldg((const __half2*)(xh + o3));
                }
                #pragma unroll
                for (int t = 0; t < 3; ++t) {
                    const int k = kb3 * 3 + t;
                    const float2 wA = __half22float2(*(const __half2*)&rv[t].z);
                    const float2 wB = __half22float2(*(const __half2*)&rv[t].w);
                    const float2 f0 = __half22float2(h[t][0]);
                    const float2 f1 = __half22float2(h[t][1]);
                    const float2 f2 = __half22float2(h[t][2]);
                    const float2 f3 = __half22float2(h[t][3]);
                    float s0 = wA.x * f0.x;
                    s0 = fmaf(wA.y, f1.x, s0);
                    s0 = fmaf(wB.x, f2.x, s0);
                    s0 = fmaf(wB.y, f3.x, s0);
                    float s1 = wA.x * f0.y;
                    s1 = fmaf(wA.y, f1.y, s1);
                    s1 = fmaf(wB.x, f2.y, s1);
                    s1 = fmaf(wB.y, f3.y, s1);

                    const uint32_t kb = (uint32_t)k * 64u + lane2;
                    const uint32_t addr = rowb + (kb & ~127u) +
                                          ((((4u * (uint32_t)k + l3) & 7u) ^ rm) << 4);
                    *(__half*)(smem + addr) = __float2half_rn(s0);
                    *(__half*)(smem + addr + ROW1_DELTA) = __float2half_rn(s1);
                }
            }
        }
    }

    __syncthreads();

    // ---- Phase 3: HMMA GEMM. 4 warps: warp w -> rows 32w..32w+31 (two 16-row groups),
    //      B fragments loaded ONCE per K-step and reused for both row groups. ----
    if (w < 4) {
        const int rowbase = w * 32;

        const int rl  = rowbase + (lane & 7) + (lane & 8);               // A row, group 0
        const int kha = (lane >> 4) & 1;                                 // A k-half
        const int nr  = (lane & 7) + (((lane >> 4) & 1) << 3);           // B row (n 0..15)
        const int khb = (lane >> 3) & 1;                                 // B k-half

        uint32_t aoff[4], boff[4];
        #pragma unroll
        for (int i = 0; i < 4; ++i) {
            aoff[i] = ((((uint32_t)(2 * i + kha)) & 7u) ^ ((uint32_t)rl & 7u)) << 4;
            boff[i] = ((((uint32_t)(2 * i + khb)) & 7u) ^ ((uint32_t)nr & 7u)) << 4;
        }
        uint32_t a_base  = sbase + SMEM_A_OFF + (uint32_t)rl * ROWB;      // group 0
        uint32_t b_base0 = sbase + SMEM_B_OFF + (uint32_t)nr * ROWB;
        uint32_t b_base1 = b_base0 + 16u * ROWB;                          // n 16..31

        float d0[16], d1[16];
        #pragma unroll
        for (int i = 0; i < 16; ++i) { d0[i] = 0.f; d1[i] = 0.f; }

        // 18 K-steps = 4 groups of 4 + 1 group of 2
        #pragma unroll
        for (int g = 0; g < 5; ++g) {
            const int steps = (g < 4) ? 4 : 2;
            #pragma unroll
            for (int i = 0; i < 4; ++i) {
                if (i >= steps) break;
                uint32_t b0, b1, b2, b3;
                LDMATRIX_X4(b0, b1, b2, b3, b_base0 + boff[i]);
                uint32_t b4, b5, b6, b7;
                LDMATRIX_X4(b4, b5, b6, b7, b_base1 + boff[i]);

                uint32_t a0, a1, a2, a3;
                LDMATRIX_X4(a0, a1, a2, a3, a_base + aoff[i]);
                MMA16816(d0 + 0,  a0, a1, a2, a3, b0, b1);
                MMA16816(d0 + 4,  a0, a1, a2, a3, b2, b3);
                MMA16816(d0 + 8,  a0, a1, a2, a3, b4, b5);
                MMA16816(d0 + 12, a0, a1, a2, a3, b6, b7);

                LDMATRIX_X4(a0, a1, a2, a3, a_base + 16u * ROWB + aoff[i]);
                MMA16816(d1 + 0,  a0, a1, a2, a3, b0, b1);
                MMA16816(d1 + 4,  a0, a1, a2, a3, b2, b3);
                MMA16816(d1 + 8,  a0, a1, a2, a3, b4, b5);
                MMA16816(d1 + 12, a0, a1, a2, a3, b6, b7);
            }
            a_base  += 128u;
            b_base0 += 128u;
            b_base1 += 128u;
        }

        // ---- Epilogue (both row groups) ----
        const int g = lane >> 2;
        const int t = lane & 3;
        #pragma unroll
        for (int rg = 0; rg < 2; ++rg) {
            const float* d = rg ? d1 : d0;
            const int R0 = rowbase + rg * 16 + g;
            const int R1 = R0 + 8;
            const int b0r = R0 >> 6, p0r = R0 & 63;
            const int b1r = R1 >> 6, p1r = R1 & 63;
            float* o0 = out + ((size_t)(b0r * HH + y) * WW + xbase + p0r) * FF;
            float* o1 = out + ((size_t)(b1r * HH + y) * WW + xbase + p1r) * FF;

            #pragma unroll
            for (int nt = 0; nt < 4; ++nt) {
                const int f0 = nt * 8 + 2 * t;
                const float2 bv = __ldg((const float2*)(bias + f0));
                float2 v0 = make_float2(d[nt * 4 + 0] + bv.x, d[nt * 4 + 1] + bv.y);
                float2 v1 = make_float2(d[nt * 4 + 2] + bv.x, d[nt * 4 + 3] + bv.y);
                *(float2*)(o0 + f0) = v0;
                *(float2*)(o1 + f0) = v1;
            }
        }
    }
}

extern "C" void kernel_launch(void* const* d_in, const int* in_sizes, int n_in,
                              void* d_out, int out_size)
{
    (void)in_sizes; (void)n_in; (void)out_size;
    const float* x    = (const float*)d_in[0];
    const float* off  = (const float*)d_in[1];
    const float* kern = (const float*)d_in[2];
    const float* bias = (const float*)d_in[3];
    float* out = (float*)d_out;

    prep_kernel<<<(NPIXC / 4 + 255) / 256, 256>>>(x, kern);

    cudaFuncSetAttribute(deform_conv_hmma,
                         cudaFuncAttributeMaxDynamicSharedMemorySize, SMEM_TOTAL);

    dim3 grid(WW / POS_PER_BLK, HH);
    deform_conv_hmma<<<grid, THREADS, SMEM_TOTAL>>>(off, bias, out);
}

// round 12
// speedup vs baseline: 4.2474x; 1.1416x over previous
#include <cuda_runtime.h>
#include <cuda_fp16.h>
#include <cstdint>

#define HH 384
#define WW 384
#define CC 32
#define FF 32
#define KK 9
#define POS_PER_BLK 64
#define THREADS 512

// A: 128 rows x 288 fp16, row padded to 640 B
#define ROWB 640u
#define SMEM_A_OFF 0u
#define A_BYTES (128u * ROWB)                  // 81920
#define ROW1_DELTA (64u * ROWB)                // batch-1 row offset
// B: 32 rows x 288 fp16, row 640 B
#define SMEM_B_OFF A_BYTES                     // 81920
#define B_BYTES (32u * ROWB)                   // 20480
#define SMEM_REC_OFF (SMEM_B_OFF + B_BYTES)    // 102400
#define REC_BYTES (576u * 16u)                 // 9216
#define SMEM_TOTAL (SMEM_REC_OFF + REC_BYTES)  // 111616  (2 CTAs/SM)

#define NPIXC (HH * WW * CC)

// Pre-swizzled fp16 B tile + batch-interleaved fp16 x image (built per launch)
__device__ __align__(16) char d_Btile[B_BYTES];
__device__ __align__(16) __half2 d_xh[NPIXC];   // [pix][c] = (x_b0, x_b1)

__device__ __forceinline__ uint32_t smem_u32(const void* p) {
    uint32_t a;
    asm("{ .reg .u64 t; cvta.to.shared.u64 t, %1; cvt.u32.u64 %0, t; }" : "=r"(a) : "l"(p));
    return a;
}

#define LDMATRIX_X4(r0, r1, r2, r3, addr)                                   \
    asm volatile("ldmatrix.sync.aligned.m8n8.x4.shared.b16 {%0,%1,%2,%3}, [%4];" \
                 : "=r"(r0), "=r"(r1), "=r"(r2), "=r"(r3) : "r"(addr))

#define MMA16816(d, a0, a1, a2, a3, b0, b1)                                 \
    asm volatile("mma.sync.aligned.m16n8k16.row.col.f32.f16.f16.f32 "       \
                 "{%0,%1,%2,%3}, {%4,%5,%6,%7}, {%8,%9}, {%0,%1,%2,%3};"    \
                 : "+f"((d)[0]), "+f"((d)[1]), "+f"((d)[2]), "+f"((d)[3])   \
                 : "r"(a0), "r"(a1), "r"(a2), "r"(a3), "r"(b0), "r"(b1))

__device__ __forceinline__ uint32_t swz_addr(uint32_t kb, uint32_t rm) {
    return (kb & ~127u) + ((((kb >> 4) & 7u) ^ rm) << 4) + (kb & 15u);
}

// ---- one merged prep: half2 x image (vectorized) + swizzled fp16 B tile ----
__global__ void prep_kernel(const float* __restrict__ x, const float* __restrict__ kern) {
    const int i = blockIdx.x * blockDim.x + threadIdx.x;
    const int base = i * 4;
    if (base < NPIXC) {
        const float4 a = __ldg((const float4*)(x + base));
        const float4 b = __ldg((const float4*)(x + NPIXC + base));
        uint4 o;
        const __half2 h0 = __floats2half2_rn(a.x, b.x);
        const __half2 h1 = __floats2half2_rn(a.y, b.y);
        const __half2 h2 = __floats2half2_rn(a.z, b.z);
        const __half2 h3 = __floats2half2_rn(a.w, b.w);
        o.x = *(const uint32_t*)&h0;
        o.y = *(const uint32_t*)&h1;
        o.z = *(const uint32_t*)&h2;
        o.w = *(const uint32_t*)&h3;
        *(uint4*)(d_xh + base) = o;
    }
    if (i < KK * CC * FF) {
        const int f = i & 31;
        const int c = (i >> 5) & 31;
        const int k = i >> 10;
        const __half wh = __float2half_rn(__ldg(kern + (k * 32 + c) * 32 + f));
        const uint32_t kb = (uint32_t)(k * 64 + c * 2);
        *(__half*)(d_Btile + (uint32_t)f * ROWB + swz_addr(kb, (uint32_t)f & 7u)) = wh;
    }
}

extern __shared__ char smem[];

__global__ __launch_bounds__(THREADS, 2)
void deform_conv_hmma(const float* __restrict__ off,
                      const float* __restrict__ bias,
                      float* __restrict__ out)
{
    const uint32_t sbase = smem_u32(smem);
    const int tid  = threadIdx.x;
    const int lane = tid & 31;
    const int w    = tid >> 5;            // 16 warps
    const int y    = blockIdx.y;
    const int xbase = blockIdx.x * POS_PER_BLK;

    // ---- B fill: straight uint4 copy ----
    #pragma unroll
    for (int i = tid; i < (int)(B_BYTES / 16); i += THREADS)
        ((uint4*)(smem + SMEM_B_OFF))[i] = ((const uint4*)d_Btile)[i];

    // ---- Stage 1: per-tap 16B records (one thread per tap; 576 taps) ----
    #pragma unroll
    for (int j = tid; j < POS_PER_BLK * KK; j += THREADS) {
        const int pos = j / KK;
        const int k   = j - pos * KK;
        const int xcol = xbase + pos;
        const float2 o = __ldg((const float2*)(off + (size_t)(y * WW + xcol) * (KK * 2) + 2 * k));

        // padded coords: tap base (y + k/3, x + k%3), pad=1, clamp to [0,385]
        float yf = fminf(fmaxf((float)(y + k / 3) + o.y, 0.f), 385.f);
        float xf = fminf(fmaxf((float)(xcol + k % 3) + o.x, 0.f), 385.f);
        const float y0f = floorf(yf), x0f = floorf(xf);
        const int y0 = (int)y0f, x0 = (int)x0f;
        const int y1 = min(y0 + 1, 385), x1 = min(x0 + 1, 385);
        const float wy0 = (float)y1 - yf, wy1 = yf - y0f;
        const float wx0 = (float)x1 - xf, wx1 = xf - x0f;

        const bool vy0 = (y0 >= 1) && (y0 <= 384);
        const bool vy1 = (y1 >= 1) && (y1 <= 384);
        const bool vx0 = (x0 >= 1) && (x0 <= 384);
        const bool vx1 = (x1 >= 1) && (x1 <= 384);
        const float w00 = (vy0 && vx0) ? wy0 * wx0 : 0.f;
        const float w01 = (vy0 && vx1) ? wy0 * wx1 : 0.f;
        const float w10 = (vy1 && vx0) ? wy1 * wx0 : 0.f;
        const float w11 = (vy1 && vx1) ? wy1 * wx1 : 0.f;

        const int y0c = min(max(y0, 1), 384), y1c = min(max(y1, 1), 384);
        const int x0c = min(max(x0, 1), 384), x1c = min(max(x1, 1), 384);
        const uint32_t i00b = (uint32_t)(((y0c - 1) * WW + (x0c - 1)) * CC) * 4u;
        const uint32_t dxb = (uint32_t)((x1c - x0c) * CC) * 4u;        // 0 or 128
        const uint32_t dyb = (uint32_t)((y1c - y0c) * WW * CC) * 4u;   // 0 or 49152

        const __half2 wA = __floats2half2_rn(w00, w01);
        const __half2 wB = __floats2half2_rn(w10, w11);
        uint4 rec;
        rec.x = i00b;
        rec.y = dxb | (dyb << 16);
        rec.z = *(const uint32_t*)&wA;
        rec.w = *(const uint32_t*)&wB;
        *(uint4*)(smem + SMEM_REC_OFF + (uint32_t)j * 16u) = rec;
    }

    __syncthreads();

    // ---- Stage 2: gather (half2 = both batches) + fp16x2 blend -> fp16 A tile ----
    const char* xh = (const char*)d_xh + (uint32_t)lane * 4u;
    {
        const uint32_t lane2 = (uint32_t)lane * 2u;
        const uint32_t l3    = (uint32_t)lane >> 3;
        #pragma unroll
        for (int p = 0; p < 4; ++p) {
            const int pos = w * 4 + p;
            const uint32_t rm = (uint32_t)pos & 7u;
            const uint32_t rowb = SMEM_A_OFF + (uint32_t)pos * ROWB + (lane2 & 15u);
            // addr(k+2) = addr(k) + 128: keep two running addresses (even/odd k)
            uint32_t adr[2];
            adr[0] = rowb + ((l3 ^ rm) << 4);
            adr[1] = rowb + ((((4u + l3) & 7u) ^ rm) << 4);
            const char* recp = smem + SMEM_REC_OFF + (uint32_t)(pos * KK) * 16u;

            #pragma unroll
            for (int kb3 = 0; kb3 < 3; ++kb3) {
                uint4 rv[3];
                #pragma unroll
                for (int t = 0; t < 3; ++t)
                    rv[t] = *(const uint4*)(recp + (kb3 * 3 + t) * 16);

                __half2 h[3][4];
                #pragma unroll
                for (int t = 0; t < 3; ++t) {
                    const uint32_t dxb = rv[t].y & 0xFFFFu;
                    const uint32_t dyb = rv[t].y >> 16;
                    const uint32_t o0 = rv[t].x;
                    const uint32_t o1 = o0 + dxb;
                    const uint32_t o2 = o0 + dyb;
                    const uint32_t o3 = o1 + dyb;
                    h[t][0] = __ldg((const __half2*)(xh + o0));
                    h[t][1] = __ldg((const __half2*)(xh + o1));
                    h[t][2] = __ldg((const __half2*)(xh + o2));
                    h[t][3] = __ldg((const __half2*)(xh + o3));
                }
                #pragma unroll
                for (int t = 0; t < 3; ++t) {
                    const int k = kb3 * 3 + t;
                    const __half2 wz = *(const __half2*)&rv[t].z;   // (w00, w01)
                    const __half2 ww = *(const __half2*)&rv[t].w;   // (w10, w11)
                    __half2 s = __hmul2(__low2half2(wz), h[t][0]);
                    s = __hfma2(__high2half2(wz), h[t][1], s);
                    s = __hfma2(__low2half2(ww),  h[t][2], s);
                    s = __hfma2(__high2half2(ww), h[t][3], s);

                    const uint32_t a = adr[k & 1];
                    *(__half*)(smem + a) = __low2half(s);                // batch 0
                    *(__half*)(smem + a + ROW1_DELTA) = __high2half(s);  // batch 1
                    adr[k & 1] += 128u;
                }
            }
        }
    }

    __syncthreads();

    // ---- Phase 3: HMMA GEMM. 4 warps: warp w -> rows 32w..32w+31 (two 16-row groups),
    //      B fragments loaded ONCE per K-step and reused for both row groups. ----
    if (w < 4) {
        const int rowbase = w * 32;

        const int rl  = rowbase + (lane & 7) + (lane & 8);               // A row, group 0
        const int kha = (lane >> 4) & 1;                                 // A k-half
        const int nr  = (lane & 7) + (((lane >> 4) & 1) << 3);           // B row (n 0..15)
        const int khb = (lane >> 3) & 1;                                 // B k-half

        uint32_t aoff[4], boff[4];
        #pragma unroll
        for (int i = 0; i < 4; ++i) {
            aoff[i] = ((((uint32_t)(2 * i + kha)) & 7u) ^ ((uint32_t)rl & 7u)) << 4;
            boff[i] = ((((uint32_t)(2 * i + khb)) & 7u) ^ ((uint32_t)nr & 7u)) << 4;
        }
        uint32_t a_base  = sbase + SMEM_A_OFF + (uint32_t)rl * ROWB;      // group 0
        uint32_t b_base0 = sbase + SMEM_B_OFF + (uint32_t)nr * ROWB;
        uint32_t b_base1 = b_base0 + 16u * ROWB;                          // n 16..31

        float d0[16], d1[16];
        #pragma unroll
        for (int i = 0; i < 16; ++i) { d0[i] = 0.f; d1[i] = 0.f; }

        // 18 K-steps = 4 groups of 4 + 1 group of 2
        #pragma unroll
        for (int g = 0; g < 5; ++g) {
            const int steps = (g < 4) ? 4 : 2;
            #pragma unroll
            for (int i = 0; i < 4; ++i) {
                if (i >= steps) break;
                uint32_t b0, b1, b2, b3;
                LDMATRIX_X4(b0, b1, b2, b3, b_base0 + boff[i]);
                uint32_t b4, b5, b6, b7;
                LDMATRIX_X4(b4, b5, b6, b7, b_base1 + boff[i]);

                uint32_t a0, a1, a2, a3;
                LDMATRIX_X4(a0, a1, a2, a3, a_base + aoff[i]);
                MMA16816(d0 + 0,  a0, a1, a2, a3, b0, b1);
                MMA16816(d0 + 4,  a0, a1, a2, a3, b2, b3);
                MMA16816(d0 + 8,  a0, a1, a2, a3, b4, b5);
                MMA16816(d0 + 12, a0, a1, a2, a3, b6, b7);

                LDMATRIX_X4(a0, a1, a2, a3, a_base + 16u * ROWB + aoff[i]);
                MMA16816(d1 + 0,  a0, a1, a2, a3, b0, b1);
                MMA16816(d1 + 4,  a0, a1, a2, a3, b2, b3);
                MMA16816(d1 + 8,  a0, a1, a2, a3, b4, b5);
                MMA16816(d1 + 12, a0, a1, a2, a3, b6, b7);
            }
            a_base  += 128u;
            b_base0 += 128u;
            b_base1 += 128u;
        }

        // ---- Epilogue (both row groups) ----
        const int g = lane >> 2;
        const int t = lane & 3;
        #pragma unroll
        for (int rg = 0; rg < 2; ++rg) {
            const float* d = rg ? d1 : d0;
            const int R0 = rowbase + rg * 16 + g;
            const int R1 = R0 + 8;
            const int b0r = R0 >> 6, p0r = R0 & 63;
            const int b1r = R1 >> 6, p1r = R1 & 63;
            float* o0 = out + ((size_t)(b0r * HH + y) * WW + xbase + p0r) * FF;
            float* o1 = out + ((size_t)(b1r * HH + y) * WW + xbase + p1r) * FF;

            #pragma unroll
            for (int nt = 0; nt < 4; ++nt) {
                const int f0 = nt * 8 + 2 * t;
                const float2 bv = __ldg((const float2*)(bias + f0));
                float2 v0 = make_float2(d[nt * 4 + 0] + bv.x, d[nt * 4 + 1] + bv.y);
                float2 v1 = make_float2(d[nt * 4 + 2] + bv.x, d[nt * 4 + 3] + bv.y);
                *(float2*)(o0 + f0) = v0;
                *(float2*)(o1 + f0) = v1;
            }
        }
    }
}

extern "C" void kernel_launch(void* const* d_in, const int* in_sizes, int n_in,
                              void* d_out, int out_size)
{
    (void)in_sizes; (void)n_in; (void)out_size;
    const float* x    = (const float*)d_in[0];
    const float* off  = (const float*)d_in[1];
    const float* kern = (const float*)d_in[2];
    const float* bias = (const float*)d_in[3];
    float* out = (float*)d_out;

    prep_kernel<<<(NPIXC / 4 + 255) / 256, 256>>>(x, kern);

    cudaFuncSetAttribute(deform_conv_hmma,
                         cudaFuncAttributeMaxDynamicSharedMemorySize, SMEM_TOTAL);

    dim3 grid(WW / POS_PER_BLK, HH);
    deform_conv_hmma<<<grid, THREADS, SMEM_TOTAL>>>(off, bias, out);
}

// round 13
// speedup vs baseline: 4.4447x; 1.0464x over previous
#include <cuda_runtime.h>
#include <cuda_fp16.h>
#include <cstdint>

#define HH 384
#define WW 384
#define CC 32
#define FF 32
#define KK 9
#define POS_PER_BLK 64
#define THREADS 512

// A: 128 rows x 288 fp16, row padded to 640 B
// K-column order: col(k,c) = (k>>1)*64 + 2c + (k&1) for k<8 ; 256 + c for k==8
#define ROWB 640u
#define SMEM_A_OFF 0u
#define A_BYTES (128u * ROWB)                  // 81920
#define ROW1_DELTA (64u * ROWB)                // batch-1 row offset
// B: 32 rows x 288 fp16, row 640 B (same K order)
#define SMEM_B_OFF A_BYTES                     // 81920
#define B_BYTES (32u * ROWB)                   // 20480
#define SMEM_REC_OFF (SMEM_B_OFF + B_BYTES)    // 102400
#define REC_BYTES (576u * 16u)                 // 9216
#define SMEM_TOTAL (SMEM_REC_OFF + REC_BYTES)  // 111616  (2 CTAs/SM)

#define NPIXC (HH * WW * CC)

// Pre-swizzled fp16 B tile + batch-interleaved fp16 x image (built per launch)
__device__ __align__(16) char d_Btile[B_BYTES];
__device__ __align__(16) __half2 d_xh[NPIXC];   // [pix][c] = (x_b0, x_b1)

__device__ __forceinline__ uint32_t smem_u32(const void* p) {
    uint32_t a;
    asm("{ .reg .u64 t; cvta.to.shared.u64 t, %1; cvt.u32.u64 %0, t; }" : "=r"(a) : "l"(p));
    return a;
}

#define LDMATRIX_X4(r0, r1, r2, r3, addr)                                   \
    asm volatile("ldmatrix.sync.aligned.m8n8.x4.shared.b16 {%0,%1,%2,%3}, [%4];" \
                 : "=r"(r0), "=r"(r1), "=r"(r2), "=r"(r3) : "r"(addr))

#define MMA16816(d, a0, a1, a2, a3, b0, b1)                                 \
    asm volatile("mma.sync.aligned.m16n8k16.row.col.f32.f16.f16.f32 "       \
                 "{%0,%1,%2,%3}, {%4,%5,%6,%7}, {%8,%9}, {%0,%1,%2,%3};"    \
                 : "+f"((d)[0]), "+f"((d)[1]), "+f"((d)[2]), "+f"((d)[3])   \
                 : "r"(a0), "r"(a1), "r"(a2), "r"(a3), "r"(b0), "r"(b1))

__device__ __forceinline__ uint32_t swz_addr(uint32_t kb, uint32_t rm) {
    return (kb & ~127u) + ((((kb >> 4) & 7u) ^ rm) << 4) + (kb & 15u);
}

// ---- one merged prep: half2 x image (vectorized) + swizzled fp16 B tile ----
__global__ void prep_kernel(const float* __restrict__ x, const float* __restrict__ kern) {
    const int i = blockIdx.x * blockDim.x + threadIdx.x;
    const int base = i * 4;
    if (base < NPIXC) {
        const float4 a = __ldg((const float4*)(x + base));
        const float4 b = __ldg((const float4*)(x + NPIXC + base));
        uint4 o;
        const __half2 h0 = __floats2half2_rn(a.x, b.x);
        const __half2 h1 = __floats2half2_rn(a.y, b.y);
        const __half2 h2 = __floats2half2_rn(a.z, b.z);
        const __half2 h3 = __floats2half2_rn(a.w, b.w);
        o.x = *(const uint32_t*)&h0;
        o.y = *(const uint32_t*)&h1;
        o.z = *(const uint32_t*)&h2;
        o.w = *(const uint32_t*)&h3;
        *(uint4*)(d_xh + base) = o;
    }
    if (i < KK * CC * FF) {
        const int f = i & 31;
        const int c = (i >> 5) & 31;
        const int k = i >> 10;
        const __half wh = __float2half_rn(__ldg(kern + (k * 32 + c) * 32 + f));
        const uint32_t kb = (k < 8)
            ? (uint32_t)((k >> 1) * 128 + c * 4 + (k & 1) * 2)
            : (uint32_t)(512 + c * 2);
        *(__half*)(d_Btile + (uint32_t)f * ROWB + swz_addr(kb, (uint32_t)f & 7u)) = wh;
    }
}

extern __shared__ char smem[];

__global__ __launch_bounds__(THREADS, 2)
void deform_conv_hmma(const float* __restrict__ off,
                      const float* __restrict__ bias,
                      float* __restrict__ out)
{
    const uint32_t sbase = smem_u32(smem);
    const int tid  = threadIdx.x;
    const int lane = tid & 31;
    const int w    = tid >> 5;            // 16 warps
    const int y    = blockIdx.y;
    const int xbase = blockIdx.x * POS_PER_BLK;

    // ---- B fill: straight uint4 copy ----
    #pragma unroll
    for (int i = tid; i < (int)(B_BYTES / 16); i += THREADS)
        ((uint4*)(smem + SMEM_B_OFF))[i] = ((const uint4*)d_Btile)[i];

    // ---- Stage 1: per-tap 16B records (one thread per tap; 576 taps) ----
    #pragma unroll
    for (int j = tid; j < POS_PER_BLK * KK; j += THREADS) {
        const int pos = j / KK;
        const int k   = j - pos * KK;
        const int xcol = xbase + pos;
        const float2 o = __ldg((const float2*)(off + (size_t)(y * WW + xcol) * (KK * 2) + 2 * k));

        // padded coords: tap base (y + k/3, x + k%3), pad=1, clamp to [0,385]
        float yf = fminf(fmaxf((float)(y + k / 3) + o.y, 0.f), 385.f);
        float xf = fminf(fmaxf((float)(xcol + k % 3) + o.x, 0.f), 385.f);
        const float y0f = floorf(yf), x0f = floorf(xf);
        const int y0 = (int)y0f, x0 = (int)x0f;
        const int y1 = min(y0 + 1, 385), x1 = min(x0 + 1, 385);
        const float wy0 = (float)y1 - yf, wy1 = yf - y0f;
        const float wx0 = (float)x1 - xf, wx1 = xf - x0f;

        const bool vy0 = (y0 >= 1) && (y0 <= 384);
        const bool vy1 = (y1 >= 1) && (y1 <= 384);
        const bool vx0 = (x0 >= 1) && (x0 <= 384);
        const bool vx1 = (x1 >= 1) && (x1 <= 384);
        const float w00 = (vy0 && vx0) ? wy0 * wx0 : 0.f;
        const float w01 = (vy0 && vx1) ? wy0 * wx1 : 0.f;
        const float w10 = (vy1 && vx0) ? wy1 * wx0 : 0.f;
        const float w11 = (vy1 && vx1) ? wy1 * wx1 : 0.f;

        const int y0c = min(max(y0, 1), 384), y1c = min(max(y1, 1), 384);
        const int x0c = min(max(x0, 1), 384), x1c = min(max(x1, 1), 384);
        const uint32_t i00b = (uint32_t)(((y0c - 1) * WW + (x0c - 1)) * CC) * 4u;
        const uint32_t dxb = (uint32_t)((x1c - x0c) * CC) * 4u;        // 0 or 128
        const uint32_t dyb = (uint32_t)((y1c - y0c) * WW * CC) * 4u;   // 0 or 49152

        const __half2 wA = __floats2half2_rn(w00, w01);
        const __half2 wB = __floats2half2_rn(w10, w11);
        uint4 rec;
        rec.x = i00b;
        rec.y = dxb | (dyb << 16);
        rec.z = *(const uint32_t*)&wA;
        rec.w = *(const uint32_t*)&wB;
        *(uint4*)(smem + SMEM_REC_OFF + (uint32_t)j * 16u) = rec;
    }

    __syncthreads();

    // ---- Stage 2: gather (half2 = both batches) + fp16x2 blend -> fp16 A tile ----
    // Pair-packed stores: taps (2j, 2j+1) for channel c are adjacent 2B -> one STS.32
    // per batch per pair (1 wavefront for the warp). Tap 8 stays STS.16.
    const char* xh = (const char*)d_xh + (uint32_t)lane * 4u;
    {
        #pragma unroll
        for (int p = 0; p < 4; ++p) {
            const int pos = w * 4 + p;
            const uint32_t rm = (uint32_t)pos & 7u;
            const uint32_t arow = SMEM_A_OFF + (uint32_t)pos * ROWB;
            // pair store: kb = j*128 + lane*4 -> block = lane>>2 (j-invariant)
            uint32_t adrP = arow + (((((uint32_t)lane >> 2)) ^ rm) << 4) +
                            ((uint32_t)lane & 3u) * 4u;
            // tap-8 store: kb = 512 + lane*2 -> block = lane>>3
            const uint32_t adr8 = arow + 512u + (((((uint32_t)lane >> 3)) ^ rm) << 4) +
                                  (((uint32_t)lane * 2u) & 15u);
            const char* recp = smem + SMEM_REC_OFF + (uint32_t)(pos * KK) * 16u;

            __half2 pend = __float2half2_rn(0.f);
            #pragma unroll
            for (int kb3 = 0; kb3 < 3; ++kb3) {
                uint4 rv[3];
                #pragma unroll
                for (int t = 0; t < 3; ++t)
                    rv[t] = *(const uint4*)(recp + (kb3 * 3 + t) * 16);

                __half2 h[3][4];
                #pragma unroll
                for (int t = 0; t < 3; ++t) {
                    const uint32_t dxb = rv[t].y & 0xFFFFu;
                    const uint32_t dyb = rv[t].y >> 16;
                    const uint32_t o0 = rv[t].x;
                    const uint32_t o1 = o0 + dxb;
                    const uint32_t o2 = o0 + dyb;
                    const uint32_t o3 = o1 + dyb;
                    h[t][0] = __ldg((const __half2*)(xh + o0));
                    h[t][1] = __ldg((const __half2*)(xh + o1));
                    h[t][2] = __ldg((const __half2*)(xh + o2));
                    h[t][3] = __ldg((const __half2*)(xh + o3));
                }
                #pragma unroll
                for (int t = 0; t < 3; ++t) {
                    const int k = kb3 * 3 + t;
                    const __half2 wz = *(const __half2*)&rv[t].z;   // (w00, w01)
                    const __half2 ww = *(const __half2*)&rv[t].w;   // (w10, w11)
                    __half2 s = __hmul2(__low2half2(wz), h[t][0]);
                    s = __hfma2(__high2half2(wz), h[t][1], s);
                    s = __hfma2(__low2half2(ww),  h[t][2], s);
                    s = __hfma2(__high2half2(ww), h[t][3], s);

                    if (k == 8) {
                        *(__half*)(smem + adr8) = __low2half(s);                // batch 0
                        *(__half*)(smem + adr8 + ROW1_DELTA) = __high2half(s);  // batch 1
                    } else if ((k & 1) == 0) {
                        pend = s;
                    } else {
                        const __half2 w0 = __lows2half2(pend, s);   // (even_b0, odd_b0)
                        const __half2 w1 = __highs2half2(pend, s);  // (even_b1, odd_b1)
                        *(__half2*)(smem + adrP) = w0;
                        *(__half2*)(smem + adrP + ROW1_DELTA) = w1;
                        adrP += 128u;
                    }
                }
            }
        }
    }

    __syncthreads();

    // ---- Phase 3: HMMA GEMM. 4 warps: warp w -> rows 32w..32w+31 (two 16-row groups),
    //      B fragments loaded ONCE per K-step and reused for both row groups. ----
    if (w < 4) {
        const int rowbase = w * 32;

        const int rl  = rowbase + (lane & 7) + (lane & 8);               // A row, group 0
        const int kha = (lane >> 4) & 1;                                 // A k-half
        const int nr  = (lane & 7) + (((lane >> 4) & 1) << 3);           // B row (n 0..15)
        const int khb = (lane >> 3) & 1;                                 // B k-half

        uint32_t aoff[4], boff[4];
        #pragma unroll
        for (int i = 0; i < 4; ++i) {
            aoff[i] = ((((uint32_t)(2 * i + kha)) & 7u) ^ ((uint32_t)rl & 7u)) << 4;
            boff[i] = ((((uint32_t)(2 * i + khb)) & 7u) ^ ((uint32_t)nr & 7u)) << 4;
        }
        uint32_t a_base  = sbase + SMEM_A_OFF + (uint32_t)rl * ROWB;      // group 0
        uint32_t b_base0 = sbase + SMEM_B_OFF + (uint32_t)nr * ROWB;
        uint32_t b_base1 = b_base0 + 16u * ROWB;                          // n 16..31

        float d0[16], d1[16];
        #pragma unroll
        for (int i = 0; i < 16; ++i) { d0[i] = 0.f; d1[i] = 0.f; }

        // 18 K-steps = 4 groups of 4 + 1 group of 2
        #pragma unroll
        for (int g = 0; g < 5; ++g) {
            const int steps = (g < 4) ? 4 : 2;
            #pragma unroll
            for (int i = 0; i < 4; ++i) {
                if (i >= steps) break;
                uint32_t b0, b1, b2, b3;
                LDMATRIX_X4(b0, b1, b2, b3, b_base0 + boff[i]);
                uint32_t b4, b5, b6, b7;
                LDMATRIX_X4(b4, b5, b6, b7, b_base1 + boff[i]);

                uint32_t a0, a1, a2, a3;
                LDMATRIX_X4(a0, a1, a2, a3, a_base + aoff[i]);
                MMA16816(d0 + 0,  a0, a1, a2, a3, b0, b1);
                MMA16816(d0 + 4,  a0, a1, a2, a3, b2, b3);
                MMA16816(d0 + 8,  a0, a1, a2, a3, b4, b5);
                MMA16816(d0 + 12, a0, a1, a2, a3, b6, b7);

                LDMATRIX_X4(a0, a1, a2, a3, a_base + 16u * ROWB + aoff[i]);
                MMA16816(d1 + 0,  a0, a1, a2, a3, b0, b1);
                MMA16816(d1 + 4,  a0, a1, a2, a3, b2, b3);
                MMA16816(d1 + 8,  a0, a1, a2, a3, b4, b5);
                MMA16816(d1 + 12, a0, a1, a2, a3, b6, b7);
            }
            a_base  += 128u;
            b_base0 += 128u;
            b_base1 += 128u;
        }

        // ---- Epilogue (both row groups) ----
        const int g = lane >> 2;
        const int t = lane & 3;
        #pragma unroll
        for (int rg = 0; rg < 2; ++rg) {
            const float* d = rg ? d1 : d0;
            const int R0 = rowbase + rg * 16 + g;
            const int R1 = R0 + 8;
            const int b0r = R0 >> 6, p0r = R0 & 63;
            const int b1r = R1 >> 6, p1r = R1 & 63;
            float* o0 = out + ((size_t)(b0r * HH + y) * WW + xbase + p0r) * FF;
            float* o1 = out + ((size_t)(b1r * HH + y) * WW + xbase + p1r) * FF;

            #pragma unroll
            for (int nt = 0; nt < 4; ++nt) {
                const int f0 = nt * 8 + 2 * t;
                const float2 bv = __ldg((const float2*)(bias + f0));
                float2 v0 = make_float2(d[nt * 4 + 0] + bv.x, d[nt * 4 + 1] + bv.y);
                float2 v1 = make_float2(d[nt * 4 + 2] + bv.x, d[nt * 4 + 3] + bv.y);
                *(float2*)(o0 + f0) = v0;
                *(float2*)(o1 + f0) = v1;
            }
        }
    }
}

extern "C" void kernel_launch(void* const* d_in, const int* in_sizes, int n_in,
                              void* d_out, int out_size)
{
    (void)in_sizes; (void)n_in; (void)out_size;
    const float* x    = (const float*)d_in[0];
    const float* off  = (const float*)d_in[1];
    const float* kern = (const float*)d_in[2];
    const float* bias = (const float*)d_in[3];
    float* out = (float*)d_out;

    prep_kernel<<<(NPIXC / 4 + 255) / 256, 256>>>(x, kern);

    cudaFuncSetAttribute(deform_conv_hmma,
                         cudaFuncAttributeMaxDynamicSharedMemorySize, SMEM_TOTAL);

    dim3 grid(WW / POS_PER_BLK, HH);
    deform_conv_hmma<<<grid, THREADS, SMEM_TOTAL>>>(off, bias, out);
}

// round 15
// speedup vs baseline: 4.4585x; 1.0031x over previous
#include <cuda_runtime.h>
#include <cuda_fp16.h>
#include <cstdint>

#define HH 384
#define WW 384
#define CC 32
#define FF 32
#define KK 9
#define POS_PER_BLK 64
#define THREADS 512

// A: 128 rows x 288 fp16, row padded to 640 B
// K-column order: col(k,c) = (k>>1)*64 + 2c + (k&1) for k<8 ; 256 + c for k==8
#define ROWB 640u
#define SMEM_A_OFF 0u
#define A_BYTES (128u * ROWB)                  // 81920
#define ROW1_DELTA (64u * ROWB)                // batch-1 row offset
// B: 32 rows x 288 fp16, row 640 B (same K order)
#define SMEM_B_OFF A_BYTES                     // 81920
#define B_BYTES (32u * ROWB)                   // 20480
#define SMEM_REC_OFF (SMEM_B_OFF + B_BYTES)    // 102400
#define REC_BYTES (576u * 16u)                 // 9216
#define SMEM_TOTAL (SMEM_REC_OFF + REC_BYTES)  // 111616  (2 CTAs/SM)

#define NPIXC (HH * WW * CC)

// Pre-swizzled fp16 B tile + batch-interleaved fp16 x image (built per launch)
__device__ __align__(16) char d_Btile[B_BYTES];
__device__ __align__(16) __half2 d_xh[NPIXC];   // [pix][c] = (x_b0, x_b1)

__device__ __forceinline__ uint32_t smem_u32(const void* p) {
    uint32_t a;
    asm("{ .reg .u64 t; cvta.to.shared.u64 t, %1; cvt.u32.u64 %0, t; }" : "=r"(a) : "l"(p));
    return a;
}

#define LDMATRIX_X4(r0, r1, r2, r3, addr)                                   \
    asm volatile("ldmatrix.sync.aligned.m8n8.x4.shared.b16 {%0,%1,%2,%3}, [%4];" \
                 : "=r"(r0), "=r"(r1), "=r"(r2), "=r"(r3) : "r"(addr))

#define MMA16816(d, a0, a1, a2, a3, b0, b1)                                 \
    asm volatile("mma.sync.aligned.m16n8k16.row.col.f32.f16.f16.f32 "       \
                 "{%0,%1,%2,%3}, {%4,%5,%6,%7}, {%8,%9}, {%0,%1,%2,%3};"    \
                 : "+f"((d)[0]), "+f"((d)[1]), "+f"((d)[2]), "+f"((d)[3])   \
                 : "r"(a0), "r"(a1), "r"(a2), "r"(a3), "r"(b0), "r"(b1))

__device__ __forceinline__ uint32_t swz_addr(uint32_t kb, uint32_t rm) {
    return (kb & ~127u) + ((((kb >> 4) & 7u) ^ rm) << 4) + (kb & 15u);
}

// ---- one merged prep: half2 x image (vectorized) + swizzled fp16 B tile ----
__global__ void prep_kernel(const float* __restrict__ x, const float* __restrict__ kern) {
    const int i = blockIdx.x * blockDim.x + threadIdx.x;
    const int base = i * 4;
    if (base < NPIXC) {
        const float4 a = __ldg((const float4*)(x + base));
        const float4 b = __ldg((const float4*)(x + NPIXC + base));
        uint4 o;
        const __half2 h0 = __floats2half2_rn(a.x, b.x);
        const __half2 h1 = __floats2half2_rn(a.y, b.y);
        const __half2 h2 = __floats2half2_rn(a.z, b.z);
        const __half2 h3 = __floats2half2_rn(a.w, b.w);
        o.x = *(const uint32_t*)&h0;
        o.y = *(const uint32_t*)&h1;
        o.z = *(const uint32_t*)&h2;
        o.w = *(const uint32_t*)&h3;
        *(uint4*)(d_xh + base) = o;
    }
    if (i < KK * CC * FF) {
        const int f = i & 31;
        const int c = (i >> 5) & 31;
        const int k = i >> 10;
        const __half wh = __float2half_rn(__ldg(kern + (k * 32 + c) * 32 + f));
        const uint32_t kb = (k < 8)
            ? (uint32_t)((k >> 1) * 128 + c * 4 + (k & 1) * 2)
            : (uint32_t)(512 + c * 2);
        *(__half*)(d_Btile + (uint32_t)f * ROWB + swz_addr(kb, (uint32_t)f & 7u)) = wh;
    }
}

extern __shared__ char smem[];

__global__ __launch_bounds__(THREADS, 2)
void deform_conv_hmma(const float* __restrict__ off,
                      const float* __restrict__ bias,
                      float* __restrict__ out)
{
    const uint32_t sbase = smem_u32(smem);
    const int tid  = threadIdx.x;
    const int lane = tid & 31;
    const int w    = tid >> 5;            // 16 warps
    const int y    = blockIdx.y;
    const int xbase = blockIdx.x * POS_PER_BLK;

    // ---- B fill: straight uint4 copy ----
    #pragma unroll
    for (int i = tid; i < (int)(B_BYTES / 16); i += THREADS)
        ((uint4*)(smem + SMEM_B_OFF))[i] = ((const uint4*)d_Btile)[i];

    // ---- Stage 1: per-tap 16B records (one thread per tap; 576 taps) ----
    #pragma unroll
    for (int j = tid; j < POS_PER_BLK * KK; j += THREADS) {
        const int pos = j / KK;
        const int k   = j - pos * KK;
        const int xcol = xbase + pos;
        const float2 o = __ldg((const float2*)(off + (size_t)(y * WW + xcol) * (KK * 2) + 2 * k));

        // padded coords: tap base (y + k/3, x + k%3), pad=1, clamp to [0,385]
        float yf = fminf(fmaxf((float)(y + k / 3) + o.y, 0.f), 385.f);
        float xf = fminf(fmaxf((float)(xcol + k % 3) + o.x, 0.f), 385.f);
        const float y0f = floorf(yf), x0f = floorf(xf);
        const int y0 = (int)y0f, x0 = (int)x0f;
        const int y1 = min(y0 + 1, 385), x1 = min(x0 + 1, 385);
        const float wy0 = (float)y1 - yf, wy1 = yf - y0f;
        const float wx0 = (float)x1 - xf, wx1 = xf - x0f;

        const bool vy0 = (y0 >= 1) && (y0 <= 384);
        const bool vy1 = (y1 >= 1) && (y1 <= 384);
        const bool vx0 = (x0 >= 1) && (x0 <= 384);
        const bool vx1 = (x1 >= 1) && (x1 <= 384);
        const float w00 = (vy0 && vx0) ? wy0 * wx0 : 0.f;
        const float w01 = (vy0 && vx1) ? wy0 * wx1 : 0.f;
        const float w10 = (vy1 && vx0) ? wy1 * wx0 : 0.f;
        const float w11 = (vy1 && vx1) ? wy1 * wx1 : 0.f;

        const int y0c = min(max(y0, 1), 384), y1c = min(max(y1, 1), 384);
        const int x0c = min(max(x0, 1), 384), x1c = min(max(x1, 1), 384);
        const uint32_t i00b = (uint32_t)(((y0c - 1) * WW + (x0c - 1)) * CC) * 4u;
        const uint32_t dxb = (uint32_t)((x1c - x0c) * CC) * 4u;        // 0 or 128
        const uint32_t dyb = (uint32_t)((y1c - y0c) * WW * CC) * 4u;   // 0 or 49152

        const __half2 wA = __floats2half2_rn(w00, w01);
        const __half2 wB = __floats2half2_rn(w10, w11);
        uint4 rec;
        rec.x = i00b;
        rec.y = dxb | (dyb << 16);
        rec.z = *(const uint32_t*)&wA;
        rec.w = *(const uint32_t*)&wB;
        *(uint4*)(smem + SMEM_REC_OFF + (uint32_t)j * 16u) = rec;
    }

    __syncthreads();

    // ---- Stage 2: gather + fp16x2 blend -> fp16 A tile (4+4+1 tap batches) ----
    const char* xh = (const char*)d_xh + (uint32_t)lane * 4u;
    {
        #pragma unroll
        for (int p = 0; p < 4; ++p) {
            const int pos = w * 4 + p;
            const uint32_t rm = (uint32_t)pos & 7u;
            const uint32_t arow = SMEM_A_OFF + (uint32_t)pos * ROWB;
            // pair store: kb = j*128 + lane*4 -> block = lane>>2 (j-invariant)
            uint32_t adrP = arow + (((((uint32_t)lane >> 2)) ^ rm) << 4) +
                            ((uint32_t)lane & 3u) * 4u;
            // tap-8 store: kb = 512 + lane*2 -> block = (kb>>4)&7 = lane>>3  (512>>4=32, 32&7=0)
            const uint32_t adr8 = arow + 512u + (((((uint32_t)lane >> 3)) ^ rm) << 4) +
                                  (((uint32_t)lane * 2u) & 15u);
            const char* recp = smem + SMEM_REC_OFF + (uint32_t)(pos * KK) * 16u;

            #pragma unroll
            for (int hb = 0; hb < 2; ++hb) {            // taps 4*hb .. 4*hb+3
                uint4 rv[4];
                #pragma unroll
                for (int t = 0; t < 4; ++t)
                    rv[t] = *(const uint4*)(recp + (hb * 4 + t) * 16);

                __half2 h[4][4];
                #pragma unroll
                for (int t = 0; t < 4; ++t) {
                    const uint32_t dxb = rv[t].y & 0xFFFFu;
                    const uint32_t dyb = rv[t].y >> 16;
                    const uint32_t o0 = rv[t].x;
                    const uint32_t o1 = o0 + dxb;
                    const uint32_t o2 = o0 + dyb;
                    const uint32_t o3 = o1 + dyb;
                    h[t][0] = __ldg((const __half2*)(xh + o0));
                    h[t][1] = __ldg((const __half2*)(xh + o1));
                    h[t][2] = __ldg((const __half2*)(xh + o2));
                    h[t][3] = __ldg((const __half2*)(xh + o3));
                }

                __half2 s[4];
                #pragma unroll
                for (int t = 0; t < 4; ++t) {
                    const __half2 wz = *(const __half2*)&rv[t].z;   // (w00, w01)
                    const __half2 ww = *(const __half2*)&rv[t].w;   // (w10, w11)
                    __half2 v = __hmul2(__low2half2(wz), h[t][0]);
                    v = __hfma2(__high2half2(wz), h[t][1], v);
                    v = __hfma2(__low2half2(ww),  h[t][2], v);
                    v = __hfma2(__high2half2(ww), h[t][3], v);
                    s[t] = v;
                }

                // two pair-stores per image half: (s0,s1) and (s2,s3)
                #pragma unroll
                for (int q = 0; q < 2; ++q) {
                    const __half2 lo = __lows2half2(s[2 * q], s[2 * q + 1]);   // batch 0
                    const __half2 hi = __highs2half2(s[2 * q], s[2 * q + 1]);  // batch 1
                    *(__half2*)(smem + adrP) = lo;
                    *(__half2*)(smem + adrP + ROW1_DELTA) = hi;
                    adrP += 128u;
                }
            }

            // tap 8 (single)
            {
                const uint4 rv = *(const uint4*)(recp + 8 * 16);
                const uint32_t dxb = rv.y & 0xFFFFu;
                const uint32_t dyb = rv.y >> 16;
                const uint32_t o0 = rv.x;
                const __half2 h0 = __ldg((const __half2*)(xh + o0));
                const __half2 h1 = __ldg((const __half2*)(xh + o0 + dxb));
                const __half2 h2 = __ldg((const __half2*)(xh + o0 + dyb));
                const __half2 h3 = __ldg((const __half2*)(xh + o0 + dxb + dyb));
                const __half2 wz = *(const __half2*)&rv.z;
                const __half2 ww = *(const __half2*)&rv.w;
                __half2 v = __hmul2(__low2half2(wz), h0);
                v = __hfma2(__high2half2(wz), h1, v);
                v = __hfma2(__low2half2(ww),  h2, v);
                v = __hfma2(__high2half2(ww), h3, v);
                *(__half*)(smem + adr8) = __low2half(v);
                *(__half*)(smem + adr8 + ROW1_DELTA) = __high2half(v);
            }
        }
    }

    __syncthreads();

    // ---- Phase 3: HMMA GEMM. 4 warps: warp w -> rows 32w..32w+31 (two 16-row groups),
    //      B fragments loaded ONCE per K-step and reused for both row groups. ----
    if (w < 4) {
        const int rowbase = w * 32;

        const int rl  = rowbase + (lane & 7) + (lane & 8);               // A row, group 0
        const int kha = (lane >> 4) & 1;                                 // A k-half
        const int nr  = (lane & 7) + (((lane >> 4) & 1) << 3);           // B row (n 0..15)
        const int khb = (lane >> 3) & 1;                                 // B k-half

        uint32_t aoff[4], boff[4];
        #pragma unroll
        for (int i = 0; i < 4; ++i) {
            aoff[i] = ((((uint32_t)(2 * i + kha)) & 7u) ^ ((uint32_t)rl & 7u)) << 4;
            boff[i] = ((((uint32_t)(2 * i + khb)) & 7u) ^ ((uint32_t)nr & 7u)) << 4;
        }
        uint32_t a_base  = sbase + SMEM_A_OFF + (uint32_t)rl * ROWB;      // group 0
        uint32_t b_base0 = sbase + SMEM_B_OFF + (uint32_t)nr * ROWB;
        uint32_t b_base1 = b_base0 + 16u * ROWB;                          // n 16..31

        float d0[16], d1[16];
        #pragma unroll
        for (int i = 0; i < 16; ++i) { d0[i] = 0.f; d1[i] = 0.f; }

        // 18 K-steps = 4 groups of 4 + 1 group of 2
        #pragma unroll
        for (int g = 0; g < 5; ++g) {
            const int steps = (g < 4) ? 4 : 2;
            #pragma unroll
            for (int i = 0; i < 4; ++i) {
                if (i >= steps) break;
                uint32_t b0, b1, b2, b3;
                LDMATRIX_X4(b0, b1, b2, b3, b_base0 + boff[i]);
                uint32_t b4, b5, b6, b7;
                LDMATRIX_X4(b4, b5, b6, b7, b_base1 + boff[i]);

                uint32_t a0, a1, a2, a3;
                LDMATRIX_X4(a0, a1, a2, a3, a_base + aoff[i]);
                MMA16816(d0 + 0,  a0, a1, a2, a3, b0, b1);
                MMA16816(d0 + 4,  a0, a1, a2, a3, b2, b3);
                MMA16816(d0 + 8,  a0, a1, a2, a3, b4, b5);
                MMA16816(d0 + 12, a0, a1, a2, a3, b6, b7);

                LDMATRIX_X4(a0, a1, a2, a3, a_base + 16u * ROWB + aoff[i]);
                MMA16816(d1 + 0,  a0, a1, a2, a3, b0, b1);
                MMA16816(d1 + 4,  a0, a1, a2, a3, b2, b3);
                MMA16816(d1 + 8,  a0, a1, a2, a3, b4, b5);
                MMA16816(d1 + 12, a0, a1, a2, a3, b6, b7);
            }
            a_base  += 128u;
            b_base0 += 128u;
            b_base1 += 128u;
        }

        // ---- Epilogue (both row groups) ----
        const int g = lane >> 2;
        const int t = lane & 3;
        #pragma unroll
        for (int rg = 0; rg < 2; ++rg) {
            const float* d = rg ? d1 : d0;
            const int R0 = rowbase + rg * 16 + g;
            const int R1 = R0 + 8;
            const int b0r = R0 >> 6, p0r = R0 & 63;
            const int b1r = R1 >> 6, p1r = R1 & 63;
            float* o0 = out + ((size_t)(b0r * HH + y) * WW + xbase + p0r) * FF;
            float* o1 = out + ((size_t)(b1r * HH + y) * WW + xbase + p1r) * FF;

            #pragma unroll
            for (int nt = 0; nt < 4; ++nt) {
                const int f0 = nt * 8 + 2 * t;
                const float2 bv = __ldg((const float2*)(bias + f0));
                float2 v0 = make_float2(d[nt * 4 + 0] + bv.x, d[nt * 4 + 1] + bv.y);
                float2 v1 = make_float2(d[nt * 4 + 2] + bv.x, d[nt * 4 + 3] + bv.y);
                *(float2*)(o0 + f0) = v0;
                *(float2*)(o1 + f0) = v1;
            }
        }
    }
}

extern "C" void kernel_launch(void* const* d_in, const int* in_sizes, int n_in,
                              void* d_out, int out_size)
{
    (void)in_sizes; (void)n_in; (void)out_size;
    const float* x    = (const float*)d_in[0];
    const float* off  = (const float*)d_in[1];
    const float* kern = (const float*)d_in[2];
    const float* bias = (const float*)d_in[3];
    float* out = (float*)d_out;

    prep_kernel<<<(NPIXC / 4 + 255) / 256, 256>>>(x, kern);

    cudaFuncSetAttribute(deform_conv_hmma,
                         cudaFuncAttributeMaxDynamicSharedMemorySize, SMEM_TOTAL);

    dim3 grid(WW / POS_PER_BLK, HH);
    deform_conv_hmma<<<grid, THREADS, SMEM_TOTAL>>>(off, bias, out);
}